// round 14
// baseline (speedup 1.0000x reference)
#include <cuda_runtime.h>
#include <cuda_bf16.h>
#include <math.h>
#include <stdint.h>

// ---------------- problem constants ----------------
#define HDIM   2048
#define NH     16
#define QLORA  1536
#define KVLORA 512
#define DN     128
#define DR     64
#define DV     128
#define QD     192
#define BB     2
#define SS     2048
#define MTOT   (BB*SS)      // 4096
#define CKVW   (KVLORA+DR)  // 576
#define KVW    (NH*(DN+DV)) // 4096
#define QW     (NH*QD)      // 3072
#define OW     (NH*DV)      // 2048

// ---------------- fp32 scratch ----------------
__device__ float d_qa  [(size_t)MTOT*QLORA];
__device__ float d_ckv [(size_t)MTOT*CKVW];

// ---------------- bf16 hi/lo scratch ----------------
__device__ __nv_bfloat16 d_hidh [(size_t)MTOT*HDIM],   d_hidl [(size_t)MTOT*HDIM];
__device__ __nv_bfloat16 d_wqah [(size_t)QLORA*HDIM],  d_wqal [(size_t)QLORA*HDIM];
__device__ __nv_bfloat16 d_wkvah[(size_t)CKVW*HDIM],   d_wkval[(size_t)CKVW*HDIM];
__device__ __nv_bfloat16 d_wqbh [(size_t)QW*QLORA],    d_wqbl [(size_t)QW*QLORA];
__device__ __nv_bfloat16 d_wkvbh[(size_t)KVW*KVLORA],  d_wkvbl[(size_t)KVW*KVLORA];
__device__ __nv_bfloat16 d_woh  [(size_t)HDIM*OW],     d_wol  [(size_t)HDIM*OW];
__device__ __nv_bfloat16 d_qanh [(size_t)MTOT*QLORA],  d_qanl [(size_t)MTOT*QLORA];
__device__ __nv_bfloat16 d_ckvnh[(size_t)MTOT*KVLORA], d_ckvnl[(size_t)MTOT*KVLORA];
__device__ __nv_bfloat16 d_qh   [(size_t)MTOT*QW],     d_ql   [(size_t)MTOT*QW];
__device__ __nv_bfloat16 d_kvh  [(size_t)MTOT*KVW],    d_kvl  [(size_t)MTOT*KVW];
__device__ __nv_bfloat16 d_kpeh [(size_t)MTOT*DR],     d_kpel [(size_t)MTOT*DR];
__device__ __nv_bfloat16 d_atth [(size_t)MTOT*OW],     d_attl [(size_t)MTOT*OW];

// ---------------- helpers ----------------
__device__ __forceinline__ uint32_t smem_u32(const void* p) {
    uint32_t a;
    asm("{ .reg .u64 t; cvta.to.shared.u64 t, %1; cvt.u32.u64 %0, t; }" : "=r"(a) : "l"(p));
    return a;
}

__device__ __forceinline__ void ldsm4(uint32_t r[4], uint32_t addr) {
    asm volatile("ldmatrix.sync.aligned.m8n8.x4.shared.b16 {%0,%1,%2,%3}, [%4];"
                 : "=r"(r[0]), "=r"(r[1]), "=r"(r[2]), "=r"(r[3]) : "r"(addr));
}

__device__ __forceinline__ void ldsm4t(uint32_t r[4], uint32_t addr) {
    asm volatile("ldmatrix.sync.aligned.m8n8.x4.trans.shared.b16 {%0,%1,%2,%3}, [%4];"
                 : "=r"(r[0]), "=r"(r[1]), "=r"(r[2]), "=r"(r[3]) : "r"(addr));
}

__device__ __forceinline__ void mma_bf16(float c[4], const uint32_t a[4],
                                         uint32_t b0, uint32_t b1) {
    asm volatile(
        "mma.sync.aligned.m16n8k16.row.col.f32.bf16.bf16.f32 "
        "{%0,%1,%2,%3}, {%4,%5,%6,%7}, {%8,%9}, {%0,%1,%2,%3};"
        : "+f"(c[0]), "+f"(c[1]), "+f"(c[2]), "+f"(c[3])
        : "r"(a[0]), "r"(a[1]), "r"(a[2]), "r"(a[3]), "r"(b0), "r"(b1));
}

__device__ __forceinline__ void split2(float x, float y, uint32_t& hp, uint32_t& lp) {
    __nv_bfloat16 hx = __float2bfloat16(x), hy = __float2bfloat16(y);
    __nv_bfloat16 lx = __float2bfloat16(x - __bfloat162float(hx));
    __nv_bfloat16 ly = __float2bfloat16(y - __bfloat162float(hy));
    hp = ((uint32_t)__bfloat16_as_ushort(hy) << 16) | __bfloat16_as_ushort(hx);
    lp = ((uint32_t)__bfloat16_as_ushort(ly) << 16) | __bfloat16_as_ushort(lx);
}

__device__ __forceinline__ uint32_t sw64(uint32_t o)   { return o ^ ((o >> 3) & 0x30); }
__device__ __forceinline__ uint32_t swz256(uint32_t o) { return o ^ (((o >> 8) & 7) << 4); }

__device__ __forceinline__ void cpa16(uint32_t dst, const void* src) {
    asm volatile("cp.async.cg.shared.global [%0], [%1], 16;" :: "r"(dst), "l"(src));
}
__device__ __forceinline__ void cpa16p(uint32_t dst, const void* src, bool valid) {
    int sz = valid ? 16 : 0;
    asm volatile("cp.async.cg.shared.global [%0], [%1], 16, %2;" :: "r"(dst), "l"(src), "r"(sz));
}
#define CPA_COMMIT() asm volatile("cp.async.commit_group;" ::: "memory")
#define CPA_WAIT1()  asm volatile("cp.async.wait_group 1;" ::: "memory")
#define CPA_WAIT0()  asm volatile("cp.async.wait_group 0;" ::: "memory")

// ---------------- merged fp32 -> bf16 hi/lo split (all 6 tensors) ----------------
__device__ __forceinline__ void split_row(const float* __restrict__ p, int cols,
                                          __nv_bfloat16* __restrict__ h,
                                          __nv_bfloat16* __restrict__ l)
{
    uint32_t* hp = reinterpret_cast<uint32_t*>(h);
    uint32_t* lp = reinterpret_cast<uint32_t*>(l);
    for (int i = threadIdx.x * 4; i < cols; i += blockDim.x * 4) {
        float4 v = *reinterpret_cast<const float4*>(p + i);
        uint32_t h0, l0, h1, l1;
        split2(v.x, v.y, h0, l0);
        split2(v.z, v.w, h1, l1);
        hp[i/2] = h0; hp[i/2+1] = h1;
        lp[i/2] = l0; lp[i/2+1] = l1;
    }
}

__global__ void splitAll_kernel(
    const float* __restrict__ hid, __nv_bfloat16* __restrict__ hidh, __nv_bfloat16* __restrict__ hidl,
    const float* __restrict__ wqa, __nv_bfloat16* __restrict__ wqah, __nv_bfloat16* __restrict__ wqal,
    const float* __restrict__ wkva, __nv_bfloat16* __restrict__ wkvah, __nv_bfloat16* __restrict__ wkval,
    const float* __restrict__ wqb, __nv_bfloat16* __restrict__ wqbh, __nv_bfloat16* __restrict__ wqbl,
    const float* __restrict__ wkvb, __nv_bfloat16* __restrict__ wkvbh, __nv_bfloat16* __restrict__ wkvbl,
    const float* __restrict__ wo, __nv_bfloat16* __restrict__ woh, __nv_bfloat16* __restrict__ wol)
{
    int r = blockIdx.x;
    if (r < MTOT) {
        split_row(hid + (size_t)r * HDIM, HDIM, hidh + (size_t)r * HDIM, hidl + (size_t)r * HDIM);
        return;
    }
    r -= MTOT;
    if (r < QLORA) {
        split_row(wqa + (size_t)r * HDIM, HDIM, wqah + (size_t)r * HDIM, wqal + (size_t)r * HDIM);
        return;
    }
    r -= QLORA;
    if (r < CKVW) {
        split_row(wkva + (size_t)r * HDIM, HDIM, wkvah + (size_t)r * HDIM, wkval + (size_t)r * HDIM);
        return;
    }
    r -= CKVW;
    if (r < QW) {
        split_row(wqb + (size_t)r * QLORA, QLORA, wqbh + (size_t)r * QLORA, wqbl + (size_t)r * QLORA);
        return;
    }
    r -= QW;
    if (r < KVW) {
        split_row(wkvb + (size_t)r * KVLORA, KVLORA, wkvbh + (size_t)r * KVLORA, wkvbl + (size_t)r * KVLORA);
        return;
    }
    r -= KVW;
    split_row(wo + (size_t)r * OW, OW, woh + (size_t)r * OW, wol + (size_t)r * OW);
}
#define SPLITALL_ROWS (MTOT + QLORA + CKVW + QW + KVW + HDIM)

// ---------------- fused RMSNorm + split (both norms, segmented) ----------------
__device__ __forceinline__ void rms_row(const float* __restrict__ p, const float* __restrict__ g,
                                        int D, __nv_bfloat16* __restrict__ h,
                                        __nv_bfloat16* __restrict__ l, float* sred)
{
    float ss = 0.f;
    for (int i = threadIdx.x; i < D; i += blockDim.x) { float v = p[i]; ss += v * v; }
    #pragma unroll
    for (int o = 16; o > 0; o >>= 1) ss += __shfl_xor_sync(0xffffffffu, ss, o);
    if ((threadIdx.x & 31) == 0) sred[threadIdx.x >> 5] = ss;
    __syncthreads();
    if (threadIdx.x < 8) {
        float v = sred[threadIdx.x];
        #pragma unroll
        for (int o = 4; o > 0; o >>= 1) v += __shfl_xor_sync(0xffu, v, o);
        if (threadIdx.x == 0) sred[0] = v;
    }
    __syncthreads();
    const float inv = rsqrtf(sred[0] / (float)D + 1e-6f);
    uint32_t* hp = reinterpret_cast<uint32_t*>(h);
    uint32_t* lp = reinterpret_cast<uint32_t*>(l);
    for (int i = threadIdx.x * 4; i < D; i += blockDim.x * 4) {
        float4 v = *reinterpret_cast<const float4*>(p + i);
        v.x *= inv * g[i]; v.y *= inv * g[i+1]; v.z *= inv * g[i+2]; v.w *= inv * g[i+3];
        uint32_t h0, l0, h1, l1;
        split2(v.x, v.y, h0, l0);
        split2(v.z, v.w, h1, l1);
        hp[i/2] = h0; hp[i/2+1] = h1;
        lp[i/2] = l0; lp[i/2+1] = l1;
    }
}

__global__ void rmsnorm2_kernel(
    const float* __restrict__ qa, const float* __restrict__ gqa,
    __nv_bfloat16* __restrict__ qanh, __nv_bfloat16* __restrict__ qanl,
    const float* __restrict__ ckv, const float* __restrict__ gkva,
    __nv_bfloat16* __restrict__ ckvnh, __nv_bfloat16* __restrict__ ckvnl)
{
    __shared__ float sred[8];
    int r = blockIdx.x;
    if (r < MTOT) {
        rms_row(qa + (size_t)r * QLORA, gqa, QLORA,
                qanh + (size_t)r * QLORA, qanl + (size_t)r * QLORA, sred);
    } else {
        r -= MTOT;
        rms_row(ckv + (size_t)r * CKVW, gkva, KVLORA,
                ckvnh + (size_t)r * KVLORA, ckvnl + (size_t)r * KVLORA, sred);
    }
}

// ---------------- bf16x3 GEMM core, 3-stage cp.async pipeline ----------------
#define GS_AH 0
#define GS_AL 8192
#define GS_BH 16384
#define GS_BL 24576
#define GS_STAGE 32768
#define GEMM_SMEM (3*GS_STAGE)

__device__ __forceinline__ void gemm_core(
    const __nv_bfloat16* __restrict__ Ah, const __nv_bfloat16* __restrict__ Al,
    const __nv_bfloat16* __restrict__ Bh, const __nv_bfloat16* __restrict__ Bl,
    float* __restrict__ C, __nv_bfloat16* __restrict__ Ch, __nv_bfloat16* __restrict__ Cl,
    int N, int K, int bm, int bn, char* sm)
{
    const uint32_t sb = smem_u32(sm);
    const int tid = threadIdx.x;
    const int NC = K >> 5;

    const int w = tid >> 5, lane = tid & 31;
    const int wm = (w & 1) * 64;
    const int wn = (w >> 1) * 32;
    const int mi  = lane >> 3;
    const int aro = (lane & 7) + (mi & 1) * 8;
    const int aks = (mi >> 1) * 8;
    const int bro = (lane & 7) + ((mi >> 1) & 1) * 8;
    const int bks = (mi & 1) * 8;

    float acc[4][4][4] = {};

    const int lr0 = tid >> 2;
    const int lc0 = tid & 3;
    const int lr1 = (256 + tid) >> 2;
    const int lc1 = (256 + tid) & 3;
    const uint32_t do0 = sw64((uint32_t)(lr0 * 64 + lc0 * 16));
    const uint32_t do1 = sw64((uint32_t)(lr1 * 64 + lc1 * 16));
    const bool bok0 = (bn + lr0) < N;
    const bool bok1 = (bn + lr1) < N;

    auto issue = [&](int c) {
        const int k0 = c << 5;
        const uint32_t st = sb + (uint32_t)(c % 3) * GS_STAGE;
        {
            const size_t go = (size_t)(bm + lr0) * K + k0 + lc0 * 8;
            cpa16(st + GS_AH + do0, Ah + go);
            cpa16(st + GS_AL + do0, Al + go);
            const size_t gb = (size_t)(bn + lr0) * K + k0 + lc0 * 8;
            cpa16p(st + GS_BH + do0, Bh + gb, bok0);
            cpa16p(st + GS_BL + do0, Bl + gb, bok0);
        }
        {
            const size_t go = (size_t)(bm + lr1) * K + k0 + lc1 * 8;
            cpa16(st + GS_AH + do1, Ah + go);
            cpa16(st + GS_AL + do1, Al + go);
            const size_t gb = (size_t)(bn + lr1) * K + k0 + lc1 * 8;
            cpa16p(st + GS_BH + do1, Bh + gb, bok1);
            cpa16p(st + GS_BL + do1, Bl + gb, bok1);
        }
        CPA_COMMIT();
    };

    auto compute = [&](int c) {
        const uint32_t st = sb + (uint32_t)(c % 3) * GS_STAGE;
        #pragma unroll
        for (int k16 = 0; k16 < 32; k16 += 16) {
            uint32_t A_h[4][4], B_h[2][4];
            #pragma unroll
            for (int f = 0; f < 4; f++) {
                const uint32_t x = (uint32_t)((wm + f * 16 + aro) * 64 + (k16 + aks) * 2);
                ldsm4(A_h[f], st + GS_AH + sw64(x));
            }
            #pragma unroll
            for (int g2 = 0; g2 < 2; g2++) {
                const uint32_t x = (uint32_t)((wn + g2 * 16 + bro) * 64 + (k16 + bks) * 2);
                ldsm4(B_h[g2], st + GS_BH + sw64(x));
            }
            #pragma unroll
            for (int f = 0; f < 4; f++)
                #pragma unroll
                for (int ni = 0; ni < 4; ni++)
                    mma_bf16(acc[f][ni], A_h[f], B_h[ni >> 1][(ni & 1) * 2],
                             B_h[ni >> 1][(ni & 1) * 2 + 1]);
            {
                uint32_t B_l[2][4];
                #pragma unroll
                for (int g2 = 0; g2 < 2; g2++) {
                    const uint32_t x = (uint32_t)((wn + g2 * 16 + bro) * 64 + (k16 + bks) * 2);
                    ldsm4(B_l[g2], st + GS_BL + sw64(x));
                }
                #pragma unroll
                for (int f = 0; f < 4; f++)
                    #pragma unroll
                    for (int ni = 0; ni < 4; ni++)
                        mma_bf16(acc[f][ni], A_h[f], B_l[ni >> 1][(ni & 1) * 2],
                                 B_l[ni >> 1][(ni & 1) * 2 + 1]);
            }
            {
                uint32_t A_l[4][4];
                #pragma unroll
                for (int f = 0; f < 4; f++) {
                    const uint32_t x = (uint32_t)((wm + f * 16 + aro) * 64 + (k16 + aks) * 2);
                    ldsm4(A_l[f], st + GS_AL + sw64(x));
                }
                #pragma unroll
                for (int f = 0; f < 4; f++)
                    #pragma unroll
                    for (int ni = 0; ni < 4; ni++)
                        mma_bf16(acc[f][ni], A_l[f], B_h[ni >> 1][(ni & 1) * 2],
                                 B_h[ni >> 1][(ni & 1) * 2 + 1]);
            }
        }
    };

    issue(0);
    issue(1);
    for (int c = 0; c < NC; c++) {
        if (c + 1 < NC) CPA_WAIT1(); else CPA_WAIT0();
        __syncthreads();
        if (c + 2 < NC) issue(c + 2);
        compute(c);
        __syncthreads();
    }

    const int gq = lane >> 2, t4 = lane & 3;
    if (C) {
        #pragma unroll
        for (int f = 0; f < 4; f++)
            #pragma unroll
            for (int ni = 0; ni < 4; ni++) {
                const int col = bn + wn + ni * 8 + t4 * 2;
                if (col < N) {
                    const int r = bm + wm + f * 16 + gq;
                    *reinterpret_cast<float2*>(&C[(size_t)r * N + col]) =
                        make_float2(acc[f][ni][0], acc[f][ni][1]);
                    *reinterpret_cast<float2*>(&C[(size_t)(r + 8) * N + col]) =
                        make_float2(acc[f][ni][2], acc[f][ni][3]);
                }
            }
    } else {
        #pragma unroll
        for (int f = 0; f < 4; f++)
            #pragma unroll
            for (int ni = 0; ni < 4; ni++) {
                const int col = bn + wn + ni * 8 + t4 * 2;
                if (col < N) {
                    const int r = bm + wm + f * 16 + gq;
                    uint32_t hp, lp;
                    split2(acc[f][ni][0], acc[f][ni][1], hp, lp);
                    *reinterpret_cast<uint32_t*>(&Ch[(size_t)r * N + col]) = hp;
                    *reinterpret_cast<uint32_t*>(&Cl[(size_t)r * N + col]) = lp;
                    split2(acc[f][ni][2], acc[f][ni][3], hp, lp);
                    *reinterpret_cast<uint32_t*>(&Ch[(size_t)(r + 8) * N + col]) = hp;
                    *reinterpret_cast<uint32_t*>(&Cl[(size_t)(r + 8) * N + col]) = lp;
                }
            }
    }
}

__global__ __launch_bounds__(256, 2) void gemm_bf(
    const __nv_bfloat16* __restrict__ Ah, const __nv_bfloat16* __restrict__ Al,
    const __nv_bfloat16* __restrict__ Bh, const __nv_bfloat16* __restrict__ Bl,
    float* __restrict__ C, __nv_bfloat16* __restrict__ Ch, __nv_bfloat16* __restrict__ Cl,
    int N, int K)
{
    extern __shared__ char sm[];
    gemm_core(Ah, Al, Bh, Bl, C, Ch, Cl, N, K, blockIdx.y * 128, blockIdx.x * 128, sm);
}

__global__ __launch_bounds__(256, 2) void gemm_dual(
    const __nv_bfloat16* __restrict__ Ah, const __nv_bfloat16* __restrict__ Al,
    const __nv_bfloat16* __restrict__ B1h, const __nv_bfloat16* __restrict__ B1l,
    float* __restrict__ C1, int N1, int split,
    const __nv_bfloat16* __restrict__ B2h, const __nv_bfloat16* __restrict__ B2l,
    float* __restrict__ C2, int N2, int K)
{
    extern __shared__ char sm[];
    const int bx = blockIdx.x;
    if (bx < split)
        gemm_core(Ah, Al, B1h, B1l, C1, nullptr, nullptr, N1, K,
                  blockIdx.y * 128, bx * 128, sm);
    else
        gemm_core(Ah, Al, B2h, B2l, C2, nullptr, nullptr, N2, K,
                  blockIdx.y * 128, (bx - split) * 128, sm);
}

// merged q+kv GEMM: both segments emit bf16 hi/lo
__global__ __launch_bounds__(256, 2) void gemm_dual2(
    const __nv_bfloat16* __restrict__ A1h, const __nv_bfloat16* __restrict__ A1l,
    const __nv_bfloat16* __restrict__ B1h, const __nv_bfloat16* __restrict__ B1l,
    __nv_bfloat16* __restrict__ C1h, __nv_bfloat16* __restrict__ C1l, int N1, int K1, int split,
    const __nv_bfloat16* __restrict__ A2h, const __nv_bfloat16* __restrict__ A2l,
    const __nv_bfloat16* __restrict__ B2h, const __nv_bfloat16* __restrict__ B2l,
    __nv_bfloat16* __restrict__ C2h, __nv_bfloat16* __restrict__ C2l, int N2, int K2)
{
    extern __shared__ char sm[];
    const int bx = blockIdx.x;
    if (bx < split)
        gemm_core(A1h, A1l, B1h, B1l, nullptr, C1h, C1l, N1, K1,
                  blockIdx.y * 128, bx * 128, sm);
    else
        gemm_core(A2h, A2l, B2h, B2l, nullptr, C2h, C2l, N2, K2,
                  blockIdx.y * 128, (bx - split) * 128, sm);
}

// ---------------- RoPE (on bf16 hi/lo q) ----------------
__global__ void rope_q_bf16(__nv_bfloat16* __restrict__ qh, __nv_bfloat16* __restrict__ ql)
{
    const int idx = blockIdx.x;
    const int row = idx / NH, h = idx % NH;
    const int t = row % SS;
    const int j = threadIdx.x;
    const double inv = exp(-log(10000.0) * (2.0 * j) / (double)DR);
    const double ang = (double)t * inv;
    const float c = (float)cos(ang), s = (float)sin(ang);
    const size_t base = (size_t)row * QW + h * QD + DN;
    const float x0 = __bfloat162float(qh[base + j]) + __bfloat162float(ql[base + j]);
    const float x1 = __bfloat162float(qh[base + j + 32]) + __bfloat162float(ql[base + j + 32]);
    const float y0 = x0 * c - x1 * s;
    const float y1 = x1 * c + x0 * s;
    __nv_bfloat16 h0 = __float2bfloat16(y0);
    __nv_bfloat16 h1 = __float2bfloat16(y1);
    qh[base + j]      = h0;
    qh[base + j + 32] = h1;
    ql[base + j]      = __float2bfloat16(y0 - __bfloat162float(h0));
    ql[base + j + 32] = __float2bfloat16(y1 - __bfloat162float(h1));
}

__global__ void rope_k_split(const float* __restrict__ ckv,
                             __nv_bfloat16* __restrict__ kpeh, __nv_bfloat16* __restrict__ kpel)
{
    const int row = blockIdx.x;
    const int t = row % SS;
    const int j = threadIdx.x;
    const double inv = exp(-log(10000.0) * (2.0 * j) / (double)DR);
    const double ang = (double)t * inv;
    const float c = (float)cos(ang), s = (float)sin(ang);
    const float* p = ckv + (size_t)row * CKVW + KVLORA;
    const float x0 = p[j], x1 = p[j + 32];
    const float y0 = x0 * c - x1 * s;
    const float y1 = x1 * c + x0 * s;
    __nv_bfloat16 h0 = __float2bfloat16(y0);
    __nv_bfloat16 h1 = __float2bfloat16(y1);
    kpeh[(size_t)row * DR + j]      = h0;
    kpeh[(size_t)row * DR + j + 32] = h1;
    kpel[(size_t)row * DR + j]      = __float2bfloat16(y0 - __bfloat162float(h0));
    kpel[(size_t)row * DR + j + 32] = __float2bfloat16(y1 - __bfloat162float(h1));
}

// ---------------- tensor-core causal flash attention (R12 structure) ----------------
// Q now cp.async'd from pre-split bf16 qh/ql; scale applied post-QK.
#define FQH 0                 // 6*8192 = 49152
#define FQL 49152
#define FKB 98304             // stage s at FKB + s*49152; KH +0, KL +24576
#define FVB 196608            // VH +0, VL +16384
#define FLASH_SMEM 229376

__global__ __launch_bounds__(256) void flash_tc(
    const __nv_bfloat16* __restrict__ qh, const __nv_bfloat16* __restrict__ ql,
    const __nv_bfloat16* __restrict__ kvh, const __nv_bfloat16* __restrict__ kvl,
    const __nv_bfloat16* __restrict__ kpeh, const __nv_bfloat16* __restrict__ kpel,
    __nv_bfloat16* __restrict__ atth, __nv_bfloat16* __restrict__ attl)
{
    extern __shared__ char sm[];
    const uint32_t sb = smem_u32(sm);

    const int qb = (int)gridDim.x - 1 - (int)blockIdx.x;   // longest-first
    const int h = blockIdx.y, b = blockIdx.z;
    const int tid = threadIdx.x;
    const int w = tid >> 5, lane = tid & 31;
    const int g = lane >> 2, t4 = lane & 3;
    const int mi  = lane >> 3;
    const int aro = (lane & 7) + (mi & 1) * 8;
    const int aks = (mi >> 1) * 8;
    const int bro = (lane & 7) + ((mi >> 1) & 1) * 8;
    const int bks = (mi & 1) * 8;
    const int hoff = h * (DN + DV);

    const int q0 = qb * 128;
    const int row0 = b * SS + q0;
    const int brow = b * SS;
    const float scale = rsqrtf((float)QD);
    const int n_tiles = 2 * qb + 2;

    auto issueK = [&](int kt) {
        const uint32_t base = sb + FKB + (kt & 1) * 49152;
        const int krow = brow + kt * 64;
        #pragma unroll
        for (int t = 0; t < 12; t++) {
            const int idx = t * 256 + tid;
            const int half = idx >= 1536;
            const int cidx = half ? idx - 1536 : idx;
            const int key = cidx / 24;
            const int c = cidx % 24;
            const int d = (c < 16) ? c * 8 : 128 + (c - 16) * 8;
            const uint32_t dst = base + (half ? 24576u : 0u) + (uint32_t)(d >> 5) * 4096
                               + sw64((uint32_t)(key * 64 + (d & 31) * 2));
            const __nv_bfloat16* src;
            if (c < 16) src = (half ? kvl : kvh) + (size_t)(krow + key) * KVW + hoff + d;
            else        src = (half ? kpel : kpeh) + (size_t)(krow + key) * DR + (d - 128);
            cpa16(dst, src);
        }
    };
    auto issueV = [&](int kt) {
        const int krow = brow + kt * 64;
        #pragma unroll
        for (int t = 0; t < 8; t++) {
            const int idx = t * 256 + tid;
            const int half = idx >= 1024;
            const int cidx = idx & 1023;
            const int key = cidx >> 4;
            const int d = (cidx & 15) * 8;
            const uint32_t dst = sb + FVB + (half ? 16384u : 0u)
                               + swz256((uint32_t)(key * 256 + d * 2));
            const __nv_bfloat16* src = (half ? kvl : kvh) + (size_t)(krow + key) * KVW + hoff + DN + d;
            cpa16(dst, src);
        }
    };

    // Q tile via cp.async: 128 rows x 24 16B-chunks per half
    #pragma unroll
    for (int t = 0; t < 24; t++) {
        const int idx = t * 256 + tid;
        const int half = idx >= 3072;
        const int cidx = half ? idx - 3072 : idx;
        const int r = cidx / 24;
        const int c = cidx % 24;
        const uint32_t dst = sb + (half ? FQL : FQH) + (uint32_t)(c >> 2) * 8192
                           + sw64((uint32_t)(r * 64 + (c & 3) * 16));
        const __nv_bfloat16* src = (half ? ql : qh) + (size_t)(row0 + r) * QW + h * QD + c * 8;
        cpa16(dst, src);
    }

    issueK(0);
    issueV(0);
    CPA_COMMIT();

    float of[16][4] = {};
    float m0 = -INFINITY, m1 = -INFINITY, l0 = 0.f, l1 = 0.f;

    for (int kt = 0; kt < n_tiles; kt++) {
        if (kt + 1 < n_tiles) { issueK(kt + 1); CPA_COMMIT(); CPA_WAIT1(); }
        else                  { CPA_WAIT0(); }
        __syncthreads();

        const int k0 = kt * 64;
        const uint32_t kbase = sb + FKB + (kt & 1) * 49152;

        // S = Q @ K^T (pass-major)
        float sf[8][4] = {};
        const uint32_t qax = (uint32_t)((w * 16 + aro) * 64 + aks * 2);
        #pragma unroll
        for (int s = 0; s < 12; s++) {
            uint32_t ah[4], al[4];
            const uint32_t qoff = (uint32_t)(s >> 1) * 8192 + sw64(qax + (s & 1) * 32);
            ldsm4(ah, sb + FQH + qoff);
            ldsm4(al, sb + FQL + qoff);
            uint32_t bh[4][4], bl[4][4];
            #pragma unroll
            for (int g2 = 0; g2 < 4; g2++) {
                const uint32_t kx = (uint32_t)((g2 * 16 + bro) * 64 + bks * 2);
                const uint32_t koff = (uint32_t)(s >> 1) * 4096 + sw64(kx + (s & 1) * 32);
                ldsm4(bh[g2], kbase + koff);
                ldsm4(bl[g2], kbase + 24576 + koff);
            }
            #pragma unroll
            for (int g2 = 0; g2 < 4; g2++)
                #pragma unroll
                for (int sub = 0; sub < 2; sub++)
                    mma_bf16(sf[g2 * 2 + sub], ah, bh[g2][sub * 2], bh[g2][sub * 2 + 1]);
            #pragma unroll
            for (int g2 = 0; g2 < 4; g2++)
                #pragma unroll
                for (int sub = 0; sub < 2; sub++)
                    mma_bf16(sf[g2 * 2 + sub], ah, bl[g2][sub * 2], bl[g2][sub * 2 + 1]);
            #pragma unroll
            for (int g2 = 0; g2 < 4; g2++)
                #pragma unroll
                for (int sub = 0; sub < 2; sub++)
                    mma_bf16(sf[g2 * 2 + sub], al, bh[g2][sub * 2], bh[g2][sub * 2 + 1]);
        }

        // apply softmax scale post-MMA
        #pragma unroll
        for (int ni = 0; ni < 8; ni++) {
            sf[ni][0] *= scale; sf[ni][1] *= scale;
            sf[ni][2] *= scale; sf[ni][3] *= scale;
        }

        if (kt >= 2 * qb) {
            const int qr0 = q0 + w * 16 + g;
            const int qr8 = qr0 + 8;
            #pragma unroll
            for (int ni = 0; ni < 8; ni++) {
                const int kp0 = k0 + ni * 8 + 2 * t4;
                const int kp1 = kp0 + 1;
                if (kp0 > qr0) sf[ni][0] = -1e30f;
                if (kp1 > qr0) sf[ni][1] = -1e30f;
                if (kp0 > qr8) sf[ni][2] = -1e30f;
                if (kp1 > qr8) sf[ni][3] = -1e30f;
            }
        }

        float tm0 = -INFINITY, tm1 = -INFINITY;
        #pragma unroll
        for (int ni = 0; ni < 8; ni++) {
            tm0 = fmaxf(tm0, fmaxf(sf[ni][0], sf[ni][1]));
            tm1 = fmaxf(tm1, fmaxf(sf[ni][2], sf[ni][3]));
        }
        #pragma unroll
        for (int o = 1; o < 4; o <<= 1) {
            tm0 = fmaxf(tm0, __shfl_xor_sync(0xffffffffu, tm0, o));
            tm1 = fmaxf(tm1, __shfl_xor_sync(0xffffffffu, tm1, o));
        }
        const float mn0 = fmaxf(m0, tm0), mn1 = fmaxf(m1, tm1);
        const float a0 = __expf(m0 - mn0), a1 = __expf(m1 - mn1);
        float ls0 = 0.f, ls1 = 0.f;
        #pragma unroll
        for (int ni = 0; ni < 8; ni++) {
            sf[ni][0] = __expf(sf[ni][0] - mn0); ls0 += sf[ni][0];
            sf[ni][1] = __expf(sf[ni][1] - mn0); ls0 += sf[ni][1];
            sf[ni][2] = __expf(sf[ni][2] - mn1); ls1 += sf[ni][2];
            sf[ni][3] = __expf(sf[ni][3] - mn1); ls1 += sf[ni][3];
        }
        #pragma unroll
        for (int o = 1; o < 4; o <<= 1) {
            ls0 += __shfl_xor_sync(0xffffffffu, ls0, o);
            ls1 += __shfl_xor_sync(0xffffffffu, ls1, o);
        }
        l0 = l0 * a0 + ls0; l1 = l1 * a1 + ls1;
        m0 = mn0; m1 = mn1;
        #pragma unroll
        for (int ni = 0; ni < 16; ni++) {
            of[ni][0] *= a0; of[ni][1] *= a0;
            of[ni][2] *= a1; of[ni][3] *= a1;
        }

        // O += P @ V (pass-major over g2 pairs)
        #pragma unroll
        for (int ks = 0; ks < 4; ks++) {
            uint32_t ph[4], pl[4];
            split2(sf[2*ks][0],   sf[2*ks][1],   ph[0], pl[0]);
            split2(sf[2*ks][2],   sf[2*ks][3],   ph[1], pl[1]);
            split2(sf[2*ks+1][0], sf[2*ks+1][1], ph[2], pl[2]);
            split2(sf[2*ks+1][2], sf[2*ks+1][3], ph[3], pl[3]);
            const int vkey = ks * 16 + (mi & 1) * 8 + (lane & 7);
            const int vdvo = (mi >> 1) * 8;
            #pragma unroll
            for (int gp = 0; gp < 4; gp++) {
                uint32_t vh[2][4], vl[2][4];
                #pragma unroll
                for (int j = 0; j < 2; j++) {
                    const int g2 = gp * 2 + j;
                    const uint32_t vo = swz256((uint32_t)(vkey * 256 + (g2 * 16 + vdvo) * 2));
                    ldsm4t(vh[j], sb + FVB + vo);
                    ldsm4t(vl[j], sb + FVB + 16384 + vo);
                }
                #pragma unroll
                for (int j = 0; j < 2; j++)
                    #pragma unroll
                    for (int sub = 0; sub < 2; sub++)
                        mma_bf16(of[(gp * 2 + j) * 2 + sub], ph, vh[j][sub * 2], vh[j][sub * 2 + 1]);
                #pragma unroll
                for (int j = 0; j < 2; j++)
                    #pragma unroll
                    for (int sub = 0; sub < 2; sub++)
                        mma_bf16(of[(gp * 2 + j) * 2 + sub], ph, vl[j][sub * 2], vl[j][sub * 2 + 1]);
                #pragma unroll
                for (int j = 0; j < 2; j++)
                    #pragma unroll
                    for (int sub = 0; sub < 2; sub++)
                        mma_bf16(of[(gp * 2 + j) * 2 + sub], pl, vh[j][sub * 2], vh[j][sub * 2 + 1]);
            }
        }
        __syncthreads();
        if (kt + 1 < n_tiles) { issueV(kt + 1); CPA_COMMIT(); }
    }

    const float il0 = 1.f / l0, il1 = 1.f / l1;
    const int rg = row0 + w * 16 + g;
    #pragma unroll
    for (int ni = 0; ni < 16; ni++) {
        const int col = h * DV + ni * 8 + t4 * 2;
        uint32_t hp, lp;
        split2(of[ni][0] * il0, of[ni][1] * il0, hp, lp);
        *reinterpret_cast<uint32_t*>(&atth[(size_t)rg * OW + col]) = hp;
        *reinterpret_cast<uint32_t*>(&attl[(size_t)rg * OW + col]) = lp;
        split2(of[ni][2] * il1, of[ni][3] * il1, hp, lp);
        *reinterpret_cast<uint32_t*>(&atth[(size_t)(rg + 8) * OW + col]) = hp;
        *reinterpret_cast<uint32_t*>(&attl[(size_t)(rg + 8) * OW + col]) = lp;
    }
}

// ---------------- launch ----------------
extern "C" void kernel_launch(void* const* d_in, const int* in_sizes, int n_in,
                              void* d_out, int out_size)
{
    (void)in_sizes; (void)n_in; (void)out_size;
    const float* hidden = (const float*)d_in[0];
    const float* w_qa   = (const float*)d_in[1];
    const float* g_qa   = (const float*)d_in[2];
    const float* w_qb   = (const float*)d_in[3];
    const float* w_kva  = (const float*)d_in[4];
    const float* g_kva  = (const float*)d_in[5];
    const float* w_kvb  = (const float*)d_in[6];
    const float* w_o    = (const float*)d_in[7];
    float* out = (float*)d_out;

    float *qa, *ckv;
    cudaGetSymbolAddress((void**)&qa,   d_qa);
    cudaGetSymbolAddress((void**)&ckv,  d_ckv);

    __nv_bfloat16 *hidh,*hidl,*wqah,*wqal,*wkvah,*wkval,*wqbh,*wqbl,*wkvbh,*wkvbl,*woh,*wol;
    __nv_bfloat16 *qanh,*qanl,*ckvnh,*ckvnl,*qhp,*qlp,*kvh,*kvl,*kpeh,*kpel,*atth,*attl;
    cudaGetSymbolAddress((void**)&hidh, d_hidh);   cudaGetSymbolAddress((void**)&hidl, d_hidl);
    cudaGetSymbolAddress((void**)&wqah, d_wqah);   cudaGetSymbolAddress((void**)&wqal, d_wqal);
    cudaGetSymbolAddress((void**)&wkvah, d_wkvah); cudaGetSymbolAddress((void**)&wkval, d_wkval);
    cudaGetSymbolAddress((void**)&wqbh, d_wqbh);   cudaGetSymbolAddress((void**)&wqbl, d_wqbl);
    cudaGetSymbolAddress((void**)&wkvbh, d_wkvbh); cudaGetSymbolAddress((void**)&wkvbl, d_wkvbl);
    cudaGetSymbolAddress((void**)&woh, d_woh);     cudaGetSymbolAddress((void**)&wol, d_wol);
    cudaGetSymbolAddress((void**)&qanh, d_qanh);   cudaGetSymbolAddress((void**)&qanl, d_qanl);
    cudaGetSymbolAddress((void**)&ckvnh, d_ckvnh); cudaGetSymbolAddress((void**)&ckvnl, d_ckvnl);
    cudaGetSymbolAddress((void**)&qhp, d_qh);      cudaGetSymbolAddress((void**)&qlp, d_ql);
    cudaGetSymbolAddress((void**)&kvh, d_kvh);     cudaGetSymbolAddress((void**)&kvl, d_kvl);
    cudaGetSymbolAddress((void**)&kpeh, d_kpeh);   cudaGetSymbolAddress((void**)&kpel, d_kpel);
    cudaGetSymbolAddress((void**)&atth, d_atth);   cudaGetSymbolAddress((void**)&attl, d_attl);

    cudaFuncSetAttribute(gemm_bf, cudaFuncAttributeMaxDynamicSharedMemorySize, GEMM_SMEM);
    cudaFuncSetAttribute(gemm_dual, cudaFuncAttributeMaxDynamicSharedMemorySize, GEMM_SMEM);
    cudaFuncSetAttribute(gemm_dual2, cudaFuncAttributeMaxDynamicSharedMemorySize, GEMM_SMEM);
    cudaFuncSetAttribute(flash_tc, cudaFuncAttributeMaxDynamicSharedMemorySize, FLASH_SMEM);

    const dim3 blk(256);

    // 1: all input splits
    splitAll_kernel<<<SPLITALL_ROWS, 256>>>(
        hidden, hidh, hidl, w_qa, wqah, wqal, w_kva, wkvah, wkval,
        w_qb, wqbh, wqbl, w_kvb, wkvbh, wkvbl, w_o, woh, wol);
    // 2: merged qa + ckv GEMM
    gemm_dual<<<dim3(QLORA/128 + (CKVW+127)/128, MTOT/128), blk, GEMM_SMEM>>>(
        hidh, hidl,
        wqah, wqal, qa, QLORA, QLORA/128,
        wkvah, wkval, ckv, CKVW, HDIM);
    // 3: both rmsnorm+split
    rmsnorm2_kernel<<<2 * MTOT, 256>>>(qa, g_qa, qanh, qanl, ckv, g_kva, ckvnh, ckvnl);
    // 4: merged q + kv GEMM (q emitted as bf16 hi/lo now)
    gemm_dual2<<<dim3(QW/128 + KVW/128, MTOT/128), blk, GEMM_SMEM>>>(
        qanh, qanl, wqbh, wqbl, qhp, qlp, QW, QLORA, QW/128,
        ckvnh, ckvnl, wkvbh, wkvbl, kvh, kvl, KVW, KVLORA);
    // 5-6: rope
    rope_q_bf16<<<MTOT * NH, 32>>>(qhp, qlp);
    rope_k_split<<<MTOT, 32>>>(ckv, kpeh, kpel);
    // 7: flash attention (R12 structure, bf16 Q via cp.async)
    flash_tc<<<dim3(SS/128, NH, BB), 256, FLASH_SMEM>>>(qhp, qlp, kvh, kvl, kpeh, kpel, atth, attl);
    // 8: out = attn @ w_o^T
    gemm_bf<<<dim3(HDIM/128, MTOT/128), blk, GEMM_SMEM>>>(atth, attl, woh, wol, out, nullptr, nullptr, HDIM, OW);
}

// round 15
// speedup vs baseline: 1.5573x; 1.5573x over previous
#include <cuda_runtime.h>
#include <cuda_bf16.h>
#include <math.h>
#include <stdint.h>

// ---------------- problem constants ----------------
#define HDIM   2048
#define NH     16
#define QLORA  1536
#define KVLORA 512
#define DN     128
#define DR     64
#define DV     128
#define QD     192
#define BB     2
#define SS     2048
#define MTOT   (BB*SS)      // 4096
#define CKVW   (KVLORA+DR)  // 576
#define KVW    (NH*(DN+DV)) // 4096
#define QW     (NH*QD)      // 3072
#define OW     (NH*DV)      // 2048

// ---------------- fp32 scratch ----------------
__device__ float d_qa  [(size_t)MTOT*QLORA];
__device__ float d_q   [(size_t)MTOT*QW];
__device__ float d_ckv [(size_t)MTOT*CKVW];

// ---------------- bf16 hi/lo scratch ----------------
__device__ __nv_bfloat16 d_hidh [(size_t)MTOT*HDIM],   d_hidl [(size_t)MTOT*HDIM];
__device__ __nv_bfloat16 d_wqah [(size_t)QLORA*HDIM],  d_wqal [(size_t)QLORA*HDIM];
__device__ __nv_bfloat16 d_wkvah[(size_t)CKVW*HDIM],   d_wkval[(size_t)CKVW*HDIM];
__device__ __nv_bfloat16 d_wqbh [(size_t)QW*QLORA],    d_wqbl [(size_t)QW*QLORA];
__device__ __nv_bfloat16 d_wkvbh[(size_t)KVW*KVLORA],  d_wkvbl[(size_t)KVW*KVLORA];
__device__ __nv_bfloat16 d_woh  [(size_t)HDIM*OW],     d_wol  [(size_t)HDIM*OW];
__device__ __nv_bfloat16 d_qanh [(size_t)MTOT*QLORA],  d_qanl [(size_t)MTOT*QLORA];
__device__ __nv_bfloat16 d_ckvnh[(size_t)MTOT*KVLORA], d_ckvnl[(size_t)MTOT*KVLORA];
__device__ __nv_bfloat16 d_kvh  [(size_t)MTOT*KVW],    d_kvl  [(size_t)MTOT*KVW];
__device__ __nv_bfloat16 d_kpeh [(size_t)MTOT*DR],     d_kpel [(size_t)MTOT*DR];
__device__ __nv_bfloat16 d_atth [(size_t)MTOT*OW],     d_attl [(size_t)MTOT*OW];

// ---------------- helpers ----------------
__device__ __forceinline__ uint32_t smem_u32(const void* p) {
    uint32_t a;
    asm("{ .reg .u64 t; cvta.to.shared.u64 t, %1; cvt.u32.u64 %0, t; }" : "=r"(a) : "l"(p));
    return a;
}

__device__ __forceinline__ void ldsm4(uint32_t r[4], uint32_t addr) {
    asm volatile("ldmatrix.sync.aligned.m8n8.x4.shared.b16 {%0,%1,%2,%3}, [%4];"
                 : "=r"(r[0]), "=r"(r[1]), "=r"(r[2]), "=r"(r[3]) : "r"(addr));
}

__device__ __forceinline__ void ldsm4t(uint32_t r[4], uint32_t addr) {
    asm volatile("ldmatrix.sync.aligned.m8n8.x4.trans.shared.b16 {%0,%1,%2,%3}, [%4];"
                 : "=r"(r[0]), "=r"(r[1]), "=r"(r[2]), "=r"(r[3]) : "r"(addr));
}

__device__ __forceinline__ void mma_bf16(float c[4], const uint32_t a[4],
                                         uint32_t b0, uint32_t b1) {
    asm volatile(
        "mma.sync.aligned.m16n8k16.row.col.f32.bf16.bf16.f32 "
        "{%0,%1,%2,%3}, {%4,%5,%6,%7}, {%8,%9}, {%0,%1,%2,%3};"
        : "+f"(c[0]), "+f"(c[1]), "+f"(c[2]), "+f"(c[3])
        : "r"(a[0]), "r"(a[1]), "r"(a[2]), "r"(a[3]), "r"(b0), "r"(b1));
}

__device__ __forceinline__ void split2(float x, float y, uint32_t& hp, uint32_t& lp) {
    __nv_bfloat16 hx = __float2bfloat16(x), hy = __float2bfloat16(y);
    __nv_bfloat16 lx = __float2bfloat16(x - __bfloat162float(hx));
    __nv_bfloat16 ly = __float2bfloat16(y - __bfloat162float(hy));
    hp = ((uint32_t)__bfloat16_as_ushort(hy) << 16) | __bfloat16_as_ushort(hx);
    lp = ((uint32_t)__bfloat16_as_ushort(ly) << 16) | __bfloat16_as_ushort(lx);
}

__device__ __forceinline__ uint32_t sw64(uint32_t o)   { return o ^ ((o >> 3) & 0x30); }
__device__ __forceinline__ uint32_t swz256(uint32_t o) { return o ^ (((o >> 8) & 7) << 4); }

__device__ __forceinline__ void cpa16(uint32_t dst, const void* src) {
    asm volatile("cp.async.cg.shared.global [%0], [%1], 16;" :: "r"(dst), "l"(src));
}
__device__ __forceinline__ void cpa16p(uint32_t dst, const void* src, bool valid) {
    int sz = valid ? 16 : 0;
    asm volatile("cp.async.cg.shared.global [%0], [%1], 16, %2;" :: "r"(dst), "l"(src), "r"(sz));
}
#define CPA_COMMIT() asm volatile("cp.async.commit_group;" ::: "memory")
#define CPA_WAIT1()  asm volatile("cp.async.wait_group 1;" ::: "memory")
#define CPA_WAIT0()  asm volatile("cp.async.wait_group 0;" ::: "memory")

// ---------------- merged fp32 -> bf16 hi/lo split (all 6 tensors) ----------------
__device__ __forceinline__ void split_row(const float* __restrict__ p, int cols,
                                          __nv_bfloat16* __restrict__ h,
                                          __nv_bfloat16* __restrict__ l)
{
    uint32_t* hp = reinterpret_cast<uint32_t*>(h);
    uint32_t* lp = reinterpret_cast<uint32_t*>(l);
    for (int i = threadIdx.x * 4; i < cols; i += blockDim.x * 4) {
        float4 v = *reinterpret_cast<const float4*>(p + i);
        uint32_t h0, l0, h1, l1;
        split2(v.x, v.y, h0, l0);
        split2(v.z, v.w, h1, l1);
        hp[i/2] = h0; hp[i/2+1] = h1;
        lp[i/2] = l0; lp[i/2+1] = l1;
    }
}

__global__ void splitAll_kernel(
    const float* __restrict__ hid, __nv_bfloat16* __restrict__ hidh, __nv_bfloat16* __restrict__ hidl,
    const float* __restrict__ wqa, __nv_bfloat16* __restrict__ wqah, __nv_bfloat16* __restrict__ wqal,
    const float* __restrict__ wkva, __nv_bfloat16* __restrict__ wkvah, __nv_bfloat16* __restrict__ wkval,
    const float* __restrict__ wqb, __nv_bfloat16* __restrict__ wqbh, __nv_bfloat16* __restrict__ wqbl,
    const float* __restrict__ wkvb, __nv_bfloat16* __restrict__ wkvbh, __nv_bfloat16* __restrict__ wkvbl,
    const float* __restrict__ wo, __nv_bfloat16* __restrict__ woh, __nv_bfloat16* __restrict__ wol)
{
    int r = blockIdx.x;
    if (r < MTOT) {
        split_row(hid + (size_t)r * HDIM, HDIM, hidh + (size_t)r * HDIM, hidl + (size_t)r * HDIM);
        return;
    }
    r -= MTOT;
    if (r < QLORA) {
        split_row(wqa + (size_t)r * HDIM, HDIM, wqah + (size_t)r * HDIM, wqal + (size_t)r * HDIM);
        return;
    }
    r -= QLORA;
    if (r < CKVW) {
        split_row(wkva + (size_t)r * HDIM, HDIM, wkvah + (size_t)r * HDIM, wkval + (size_t)r * HDIM);
        return;
    }
    r -= CKVW;
    if (r < QW) {
        split_row(wqb + (size_t)r * QLORA, QLORA, wqbh + (size_t)r * QLORA, wqbl + (size_t)r * QLORA);
        return;
    }
    r -= QW;
    if (r < KVW) {
        split_row(wkvb + (size_t)r * KVLORA, KVLORA, wkvbh + (size_t)r * KVLORA, wkvbl + (size_t)r * KVLORA);
        return;
    }
    r -= KVW;
    split_row(wo + (size_t)r * OW, OW, woh + (size_t)r * OW, wol + (size_t)r * OW);
}
#define SPLITALL_ROWS (MTOT + QLORA + CKVW + QW + KVW + HDIM)

// ---------------- fused RMSNorm + split (both norms, segmented) ----------------
__device__ __forceinline__ void rms_row(const float* __restrict__ p, const float* __restrict__ g,
                                        int D, __nv_bfloat16* __restrict__ h,
                                        __nv_bfloat16* __restrict__ l, float* sred)
{
    float ss = 0.f;
    for (int i = threadIdx.x; i < D; i += blockDim.x) { float v = p[i]; ss += v * v; }
    #pragma unroll
    for (int o = 16; o > 0; o >>= 1) ss += __shfl_xor_sync(0xffffffffu, ss, o);
    if ((threadIdx.x & 31) == 0) sred[threadIdx.x >> 5] = ss;
    __syncthreads();
    if (threadIdx.x < 8) {
        float v = sred[threadIdx.x];
        #pragma unroll
        for (int o = 4; o > 0; o >>= 1) v += __shfl_xor_sync(0xffu, v, o);
        if (threadIdx.x == 0) sred[0] = v;
    }
    __syncthreads();
    const float inv = rsqrtf(sred[0] / (float)D + 1e-6f);
    uint32_t* hp = reinterpret_cast<uint32_t*>(h);
    uint32_t* lp = reinterpret_cast<uint32_t*>(l);
    for (int i = threadIdx.x * 4; i < D; i += blockDim.x * 4) {
        float4 v = *reinterpret_cast<const float4*>(p + i);
        v.x *= inv * g[i]; v.y *= inv * g[i+1]; v.z *= inv * g[i+2]; v.w *= inv * g[i+3];
        uint32_t h0, l0, h1, l1;
        split2(v.x, v.y, h0, l0);
        split2(v.z, v.w, h1, l1);
        hp[i/2] = h0; hp[i/2+1] = h1;
        lp[i/2] = l0; lp[i/2+1] = l1;
    }
}

__global__ void rmsnorm2_kernel(
    const float* __restrict__ qa, const float* __restrict__ gqa,
    __nv_bfloat16* __restrict__ qanh, __nv_bfloat16* __restrict__ qanl,
    const float* __restrict__ ckv, const float* __restrict__ gkva,
    __nv_bfloat16* __restrict__ ckvnh, __nv_bfloat16* __restrict__ ckvnl)
{
    __shared__ float sred[8];
    int r = blockIdx.x;
    if (r < MTOT) {
        rms_row(qa + (size_t)r * QLORA, gqa, QLORA,
                qanh + (size_t)r * QLORA, qanl + (size_t)r * QLORA, sred);
    } else {
        r -= MTOT;
        rms_row(ckv + (size_t)r * CKVW, gkva, KVLORA,
                ckvnh + (size_t)r * KVLORA, ckvnl + (size_t)r * KVLORA, sred);
    }
}

// ---------------- bf16x3 GEMM core, 3-stage cp.async pipeline ----------------
#define GS_AH 0
#define GS_AL 8192
#define GS_BH 16384
#define GS_BL 24576
#define GS_STAGE 32768
#define GEMM_SMEM (3*GS_STAGE)

__device__ __forceinline__ void gemm_core(
    const __nv_bfloat16* __restrict__ Ah, const __nv_bfloat16* __restrict__ Al,
    const __nv_bfloat16* __restrict__ Bh, const __nv_bfloat16* __restrict__ Bl,
    float* __restrict__ C, __nv_bfloat16* __restrict__ Ch, __nv_bfloat16* __restrict__ Cl,
    int N, int K, int bm, int bn, char* sm)
{
    const uint32_t sb = smem_u32(sm);
    const int tid = threadIdx.x;
    const int NC = K >> 5;

    const int w = tid >> 5, lane = tid & 31;
    const int wm = (w & 1) * 64;
    const int wn = (w >> 1) * 32;
    const int mi  = lane >> 3;
    const int aro = (lane & 7) + (mi & 1) * 8;
    const int aks = (mi >> 1) * 8;
    const int bro = (lane & 7) + ((mi >> 1) & 1) * 8;
    const int bks = (mi & 1) * 8;

    float acc[4][4][4] = {};

    const int lr0 = tid >> 2;
    const int lc0 = tid & 3;
    const int lr1 = (256 + tid) >> 2;
    const int lc1 = (256 + tid) & 3;
    const uint32_t do0 = sw64((uint32_t)(lr0 * 64 + lc0 * 16));
    const uint32_t do1 = sw64((uint32_t)(lr1 * 64 + lc1 * 16));
    const bool bok0 = (bn + lr0) < N;
    const bool bok1 = (bn + lr1) < N;

    auto issue = [&](int c) {
        const int k0 = c << 5;
        const uint32_t st = sb + (uint32_t)(c % 3) * GS_STAGE;
        {
            const size_t go = (size_t)(bm + lr0) * K + k0 + lc0 * 8;
            cpa16(st + GS_AH + do0, Ah + go);
            cpa16(st + GS_AL + do0, Al + go);
            const size_t gb = (size_t)(bn + lr0) * K + k0 + lc0 * 8;
            cpa16p(st + GS_BH + do0, Bh + gb, bok0);
            cpa16p(st + GS_BL + do0, Bl + gb, bok0);
        }
        {
            const size_t go = (size_t)(bm + lr1) * K + k0 + lc1 * 8;
            cpa16(st + GS_AH + do1, Ah + go);
            cpa16(st + GS_AL + do1, Al + go);
            const size_t gb = (size_t)(bn + lr1) * K + k0 + lc1 * 8;
            cpa16p(st + GS_BH + do1, Bh + gb, bok1);
            cpa16p(st + GS_BL + do1, Bl + gb, bok1);
        }
        CPA_COMMIT();
    };

    auto compute = [&](int c) {
        const uint32_t st = sb + (uint32_t)(c % 3) * GS_STAGE;
        #pragma unroll
        for (int k16 = 0; k16 < 32; k16 += 16) {
            uint32_t A_h[4][4], B_h[2][4];
            #pragma unroll
            for (int f = 0; f < 4; f++) {
                const uint32_t x = (uint32_t)((wm + f * 16 + aro) * 64 + (k16 + aks) * 2);
                ldsm4(A_h[f], st + GS_AH + sw64(x));
            }
            #pragma unroll
            for (int g2 = 0; g2 < 2; g2++) {
                const uint32_t x = (uint32_t)((wn + g2 * 16 + bro) * 64 + (k16 + bks) * 2);
                ldsm4(B_h[g2], st + GS_BH + sw64(x));
            }
            #pragma unroll
            for (int f = 0; f < 4; f++)
                #pragma unroll
                for (int ni = 0; ni < 4; ni++)
                    mma_bf16(acc[f][ni], A_h[f], B_h[ni >> 1][(ni & 1) * 2],
                             B_h[ni >> 1][(ni & 1) * 2 + 1]);
            {
                uint32_t B_l[2][4];
                #pragma unroll
                for (int g2 = 0; g2 < 2; g2++) {
                    const uint32_t x = (uint32_t)((wn + g2 * 16 + bro) * 64 + (k16 + bks) * 2);
                    ldsm4(B_l[g2], st + GS_BL + sw64(x));
                }
                #pragma unroll
                for (int f = 0; f < 4; f++)
                    #pragma unroll
                    for (int ni = 0; ni < 4; ni++)
                        mma_bf16(acc[f][ni], A_h[f], B_l[ni >> 1][(ni & 1) * 2],
                                 B_l[ni >> 1][(ni & 1) * 2 + 1]);
            }
            {
                uint32_t A_l[4][4];
                #pragma unroll
                for (int f = 0; f < 4; f++) {
                    const uint32_t x = (uint32_t)((wm + f * 16 + aro) * 64 + (k16 + aks) * 2);
                    ldsm4(A_l[f], st + GS_AL + sw64(x));
                }
                #pragma unroll
                for (int f = 0; f < 4; f++)
                    #pragma unroll
                    for (int ni = 0; ni < 4; ni++)
                        mma_bf16(acc[f][ni], A_l[f], B_h[ni >> 1][(ni & 1) * 2],
                                 B_h[ni >> 1][(ni & 1) * 2 + 1]);
            }
        }
    };

    issue(0);
    issue(1);
    for (int c = 0; c < NC; c++) {
        if (c + 1 < NC) CPA_WAIT1(); else CPA_WAIT0();
        __syncthreads();
        if (c + 2 < NC) issue(c + 2);
        compute(c);
        __syncthreads();
    }

    const int gq = lane >> 2, t4 = lane & 3;
    if (C) {
        #pragma unroll
        for (int f = 0; f < 4; f++)
            #pragma unroll
            for (int ni = 0; ni < 4; ni++) {
                const int col = bn + wn + ni * 8 + t4 * 2;
                if (col < N) {
                    const int r = bm + wm + f * 16 + gq;
                    *reinterpret_cast<float2*>(&C[(size_t)r * N + col]) =
                        make_float2(acc[f][ni][0], acc[f][ni][1]);
                    *reinterpret_cast<float2*>(&C[(size_t)(r + 8) * N + col]) =
                        make_float2(acc[f][ni][2], acc[f][ni][3]);
                }
            }
    } else {
        #pragma unroll
        for (int f = 0; f < 4; f++)
            #pragma unroll
            for (int ni = 0; ni < 4; ni++) {
                const int col = bn + wn + ni * 8 + t4 * 2;
                if (col < N) {
                    const int r = bm + wm + f * 16 + gq;
                    uint32_t hp, lp;
                    split2(acc[f][ni][0], acc[f][ni][1], hp, lp);
                    *reinterpret_cast<uint32_t*>(&Ch[(size_t)r * N + col]) = hp;
                    *reinterpret_cast<uint32_t*>(&Cl[(size_t)r * N + col]) = lp;
                    split2(acc[f][ni][2], acc[f][ni][3], hp, lp);
                    *reinterpret_cast<uint32_t*>(&Ch[(size_t)(r + 8) * N + col]) = hp;
                    *reinterpret_cast<uint32_t*>(&Cl[(size_t)(r + 8) * N + col]) = lp;
                }
            }
    }
}

__global__ __launch_bounds__(256, 2) void gemm_bf(
    const __nv_bfloat16* __restrict__ Ah, const __nv_bfloat16* __restrict__ Al,
    const __nv_bfloat16* __restrict__ Bh, const __nv_bfloat16* __restrict__ Bl,
    float* __restrict__ C, __nv_bfloat16* __restrict__ Ch, __nv_bfloat16* __restrict__ Cl,
    int N, int K)
{
    extern __shared__ char sm[];
    gemm_core(Ah, Al, Bh, Bl, C, Ch, Cl, N, K, blockIdx.y * 128, blockIdx.x * 128, sm);
}

__global__ __launch_bounds__(256, 2) void gemm_dual(
    const __nv_bfloat16* __restrict__ Ah, const __nv_bfloat16* __restrict__ Al,
    const __nv_bfloat16* __restrict__ B1h, const __nv_bfloat16* __restrict__ B1l,
    float* __restrict__ C1, int N1, int split,
    const __nv_bfloat16* __restrict__ B2h, const __nv_bfloat16* __restrict__ B2l,
    float* __restrict__ C2, int N2, int K)
{
    extern __shared__ char sm[];
    const int bx = blockIdx.x;
    if (bx < split)
        gemm_core(Ah, Al, B1h, B1l, C1, nullptr, nullptr, N1, K,
                  blockIdx.y * 128, bx * 128, sm);
    else
        gemm_core(Ah, Al, B2h, B2l, C2, nullptr, nullptr, N2, K,
                  blockIdx.y * 128, (bx - split) * 128, sm);
}

__global__ __launch_bounds__(256, 2) void gemm_dual2(
    const __nv_bfloat16* __restrict__ A1h, const __nv_bfloat16* __restrict__ A1l,
    const __nv_bfloat16* __restrict__ B1h, const __nv_bfloat16* __restrict__ B1l,
    float* __restrict__ C1, int N1, int K1, int split,
    const __nv_bfloat16* __restrict__ A2h, const __nv_bfloat16* __restrict__ A2l,
    const __nv_bfloat16* __restrict__ B2h, const __nv_bfloat16* __restrict__ B2l,
    __nv_bfloat16* __restrict__ C2h, __nv_bfloat16* __restrict__ C2l, int N2, int K2)
{
    extern __shared__ char sm[];
    const int bx = blockIdx.x;
    if (bx < split)
        gemm_core(A1h, A1l, B1h, B1l, C1, nullptr, nullptr, N1, K1,
                  blockIdx.y * 128, bx * 128, sm);
    else
        gemm_core(A2h, A2l, B2h, B2l, nullptr, C2h, C2l, N2, K2,
                  blockIdx.y * 128, (bx - split) * 128, sm);
}

// ---------------- merged RoPE (q segment + k segment) ----------------
__global__ void rope2_kernel(float* __restrict__ q, const float* __restrict__ ckv,
                             __nv_bfloat16* __restrict__ kpeh, __nv_bfloat16* __restrict__ kpel)
{
    const int j = threadIdx.x;
    const double inv = exp(-log(10000.0) * (2.0 * j) / (double)DR);
    if (blockIdx.x < MTOT * NH) {
        const int idx = blockIdx.x;
        const int row = idx / NH, h = idx % NH;
        const int t = row % SS;
        const double ang = (double)t * inv;
        const float c = (float)cos(ang), s = (float)sin(ang);
        float* p = q + (size_t)row * QW + h * QD + DN;
        const float x0 = p[j], x1 = p[j + 32];
        p[j]      = x0 * c - x1 * s;
        p[j + 32] = x1 * c + x0 * s;
    } else {
        const int row = blockIdx.x - MTOT * NH;
        const int t = row % SS;
        const double ang = (double)t * inv;
        const float c = (float)cos(ang), s = (float)sin(ang);
        const float* p = ckv + (size_t)row * CKVW + KVLORA;
        const float x0 = p[j], x1 = p[j + 32];
        const float y0 = x0 * c - x1 * s;
        const float y1 = x1 * c + x0 * s;
        __nv_bfloat16 h0 = __float2bfloat16(y0);
        __nv_bfloat16 h1 = __float2bfloat16(y1);
        kpeh[(size_t)row * DR + j]      = h0;
        kpeh[(size_t)row * DR + j + 32] = h1;
        kpel[(size_t)row * DR + j]      = __float2bfloat16(y0 - __bfloat162float(h0));
        kpel[(size_t)row * DR + j + 32] = __float2bfloat16(y1 - __bfloat162float(h1));
    }
}

// ---------------- tensor-core causal flash attention (R12) ----------------
#define FQH 0                 // 6*8192 = 49152
#define FQL 49152
#define FKB 98304             // stage s at FKB + s*49152; KH +0, KL +24576
#define FVB 196608            // VH +0, VL +16384
#define FLASH_SMEM 229376

__global__ __launch_bounds__(256) void flash_tc(
    const float* __restrict__ q,
    const __nv_bfloat16* __restrict__ kvh, const __nv_bfloat16* __restrict__ kvl,
    const __nv_bfloat16* __restrict__ kpeh, const __nv_bfloat16* __restrict__ kpel,
    __nv_bfloat16* __restrict__ atth, __nv_bfloat16* __restrict__ attl)
{
    extern __shared__ char sm[];
    const uint32_t sb = smem_u32(sm);

    const int qb = (int)gridDim.x - 1 - (int)blockIdx.x;   // longest-first
    const int h = blockIdx.y, b = blockIdx.z;
    const int tid = threadIdx.x;
    const int w = tid >> 5, lane = tid & 31;
    const int g = lane >> 2, t4 = lane & 3;
    const int mi  = lane >> 3;
    const int aro = (lane & 7) + (mi & 1) * 8;
    const int aks = (mi >> 1) * 8;
    const int bro = (lane & 7) + ((mi >> 1) & 1) * 8;
    const int bks = (mi & 1) * 8;
    const int hoff = h * (DN + DV);

    const int q0 = qb * 128;
    const int row0 = b * SS + q0;
    const int brow = b * SS;
    const float scale = rsqrtf((float)QD);
    const int n_tiles = 2 * qb + 2;

    auto issueK = [&](int kt) {
        const uint32_t base = sb + FKB + (kt & 1) * 49152;
        const int krow = brow + kt * 64;
        #pragma unroll
        for (int t = 0; t < 12; t++) {
            const int idx = t * 256 + tid;
            const int half = idx >= 1536;
            const int cidx = half ? idx - 1536 : idx;
            const int key = cidx / 24;
            const int c = cidx % 24;
            const int d = (c < 16) ? c * 8 : 128 + (c - 16) * 8;
            const uint32_t dst = base + (half ? 24576u : 0u) + (uint32_t)(d >> 5) * 4096
                               + sw64((uint32_t)(key * 64 + (d & 31) * 2));
            const __nv_bfloat16* src;
            if (c < 16) src = (half ? kvl : kvh) + (size_t)(krow + key) * KVW + hoff + d;
            else        src = (half ? kpel : kpeh) + (size_t)(krow + key) * DR + (d - 128);
            cpa16(dst, src);
        }
    };
    auto issueV = [&](int kt) {
        const int krow = brow + kt * 64;
        #pragma unroll
        for (int t = 0; t < 8; t++) {
            const int idx = t * 256 + tid;
            const int half = idx >= 1024;
            const int cidx = idx & 1023;
            const int key = cidx >> 4;
            const int d = (cidx & 15) * 8;
            const uint32_t dst = sb + FVB + (half ? 16384u : 0u)
                               + swz256((uint32_t)(key * 256 + d * 2));
            const __nv_bfloat16* src = (half ? kvl : kvh) + (size_t)(krow + key) * KVW + hoff + DN + d;
            cpa16(dst, src);
        }
    };

    #pragma unroll
    for (int t = 0; t < 24; t++) {
        const int idx = t * 256 + tid;
        const int r = idx / 48;
        const int c4 = (idx % 48) * 4;
        float4 v = *reinterpret_cast<const float4*>(&q[(size_t)(row0 + r) * QW + h * QD + c4]);
        v.x *= scale; v.y *= scale; v.z *= scale; v.w *= scale;
        const uint32_t off = (uint32_t)(c4 >> 5) * 8192 + sw64((uint32_t)(r * 64 + (c4 & 31) * 2));
        uint32_t h0, l0, h1, l1;
        split2(v.x, v.y, h0, l0);
        split2(v.z, v.w, h1, l1);
        *reinterpret_cast<uint2*>(sm + FQH + off) = make_uint2(h0, h1);
        *reinterpret_cast<uint2*>(sm + FQL + off) = make_uint2(l0, l1);
    }

    issueK(0);
    issueV(0);
    CPA_COMMIT();

    float of[16][4] = {};
    float m0 = -INFINITY, m1 = -INFINITY, l0 = 0.f, l1 = 0.f;

    for (int kt = 0; kt < n_tiles; kt++) {
        if (kt + 1 < n_tiles) { issueK(kt + 1); CPA_COMMIT(); CPA_WAIT1(); }
        else                  { CPA_WAIT0(); }
        __syncthreads();

        const int k0 = kt * 64;
        const uint32_t kbase = sb + FKB + (kt & 1) * 49152;

        float sf[8][4] = {};
        const uint32_t qax = (uint32_t)((w * 16 + aro) * 64 + aks * 2);
        #pragma unroll
        for (int s = 0; s < 12; s++) {
            uint32_t ah[4], al[4];
            const uint32_t qoff = (uint32_t)(s >> 1) * 8192 + sw64(qax + (s & 1) * 32);
            ldsm4(ah, sb + FQH + qoff);
            ldsm4(al, sb + FQL + qoff);
            uint32_t bh[4][4], bl[4][4];
            #pragma unroll
            for (int g2 = 0; g2 < 4; g2++) {
                const uint32_t kx = (uint32_t)((g2 * 16 + bro) * 64 + bks * 2);
                const uint32_t koff = (uint32_t)(s >> 1) * 4096 + sw64(kx + (s & 1) * 32);
                ldsm4(bh[g2], kbase + koff);
                ldsm4(bl[g2], kbase + 24576 + koff);
            }
            #pragma unroll
            for (int g2 = 0; g2 < 4; g2++)
                #pragma unroll
                for (int sub = 0; sub < 2; sub++)
                    mma_bf16(sf[g2 * 2 + sub], ah, bh[g2][sub * 2], bh[g2][sub * 2 + 1]);
            #pragma unroll
            for (int g2 = 0; g2 < 4; g2++)
                #pragma unroll
                for (int sub = 0; sub < 2; sub++)
                    mma_bf16(sf[g2 * 2 + sub], ah, bl[g2][sub * 2], bl[g2][sub * 2 + 1]);
            #pragma unroll
            for (int g2 = 0; g2 < 4; g2++)
                #pragma unroll
                for (int sub = 0; sub < 2; sub++)
                    mma_bf16(sf[g2 * 2 + sub], al, bh[g2][sub * 2], bh[g2][sub * 2 + 1]);
        }

        if (kt >= 2 * qb) {
            const int qr0 = q0 + w * 16 + g;
            const int qr8 = qr0 + 8;
            #pragma unroll
            for (int ni = 0; ni < 8; ni++) {
                const int kp0 = k0 + ni * 8 + 2 * t4;
                const int kp1 = kp0 + 1;
                if (kp0 > qr0) sf[ni][0] = -1e30f;
                if (kp1 > qr0) sf[ni][1] = -1e30f;
                if (kp0 > qr8) sf[ni][2] = -1e30f;
                if (kp1 > qr8) sf[ni][3] = -1e30f;
            }
        }

        float tm0 = -INFINITY, tm1 = -INFINITY;
        #pragma unroll
        for (int ni = 0; ni < 8; ni++) {
            tm0 = fmaxf(tm0, fmaxf(sf[ni][0], sf[ni][1]));
            tm1 = fmaxf(tm1, fmaxf(sf[ni][2], sf[ni][3]));
        }
        #pragma unroll
        for (int o = 1; o < 4; o <<= 1) {
            tm0 = fmaxf(tm0, __shfl_xor_sync(0xffffffffu, tm0, o));
            tm1 = fmaxf(tm1, __shfl_xor_sync(0xffffffffu, tm1, o));
        }
        const float mn0 = fmaxf(m0, tm0), mn1 = fmaxf(m1, tm1);
        const float a0 = __expf(m0 - mn0), a1 = __expf(m1 - mn1);
        float ls0 = 0.f, ls1 = 0.f;
        #pragma unroll
        for (int ni = 0; ni < 8; ni++) {
            sf[ni][0] = __expf(sf[ni][0] - mn0); ls0 += sf[ni][0];
            sf[ni][1] = __expf(sf[ni][1] - mn0); ls0 += sf[ni][1];
            sf[ni][2] = __expf(sf[ni][2] - mn1); ls1 += sf[ni][2];
            sf[ni][3] = __expf(sf[ni][3] - mn1); ls1 += sf[ni][3];
        }
        #pragma unroll
        for (int o = 1; o < 4; o <<= 1) {
            ls0 += __shfl_xor_sync(0xffffffffu, ls0, o);
            ls1 += __shfl_xor_sync(0xffffffffu, ls1, o);
        }
        l0 = l0 * a0 + ls0; l1 = l1 * a1 + ls1;
        m0 = mn0; m1 = mn1;
        #pragma unroll
        for (int ni = 0; ni < 16; ni++) {
            of[ni][0] *= a0; of[ni][1] *= a0;
            of[ni][2] *= a1; of[ni][3] *= a1;
        }

        #pragma unroll
        for (int ks = 0; ks < 4; ks++) {
            uint32_t ph[4], pl[4];
            split2(sf[2*ks][0],   sf[2*ks][1],   ph[0], pl[0]);
            split2(sf[2*ks][2],   sf[2*ks][3],   ph[1], pl[1]);
            split2(sf[2*ks+1][0], sf[2*ks+1][1], ph[2], pl[2]);
            split2(sf[2*ks+1][2], sf[2*ks+1][3], ph[3], pl[3]);
            const int vkey = ks * 16 + (mi & 1) * 8 + (lane & 7);
            const int vdvo = (mi >> 1) * 8;
            #pragma unroll
            for (int gp = 0; gp < 4; gp++) {
                uint32_t vh[2][4], vl[2][4];
                #pragma unroll
                for (int j = 0; j < 2; j++) {
                    const int g2 = gp * 2 + j;
                    const uint32_t vo = swz256((uint32_t)(vkey * 256 + (g2 * 16 + vdvo) * 2));
                    ldsm4t(vh[j], sb + FVB + vo);
                    ldsm4t(vl[j], sb + FVB + 16384 + vo);
                }
                #pragma unroll
                for (int j = 0; j < 2; j++)
                    #pragma unroll
                    for (int sub = 0; sub < 2; sub++)
                        mma_bf16(of[(gp * 2 + j) * 2 + sub], ph, vh[j][sub * 2], vh[j][sub * 2 + 1]);
                #pragma unroll
                for (int j = 0; j < 2; j++)
                    #pragma unroll
                    for (int sub = 0; sub < 2; sub++)
                        mma_bf16(of[(gp * 2 + j) * 2 + sub], ph, vl[j][sub * 2], vl[j][sub * 2 + 1]);
                #pragma unroll
                for (int j = 0; j < 2; j++)
                    #pragma unroll
                    for (int sub = 0; sub < 2; sub++)
                        mma_bf16(of[(gp * 2 + j) * 2 + sub], pl, vh[j][sub * 2], vh[j][sub * 2 + 1]);
            }
        }
        __syncthreads();
        if (kt + 1 < n_tiles) { issueV(kt + 1); CPA_COMMIT(); }
    }

    const float il0 = 1.f / l0, il1 = 1.f / l1;
    const int rg = row0 + w * 16 + g;
    #pragma unroll
    for (int ni = 0; ni < 16; ni++) {
        const int col = h * DV + ni * 8 + t4 * 2;
        uint32_t hp, lp;
        split2(of[ni][0] * il0, of[ni][1] * il0, hp, lp);
        *reinterpret_cast<uint32_t*>(&atth[(size_t)rg * OW + col]) = hp;
        *reinterpret_cast<uint32_t*>(&attl[(size_t)rg * OW + col]) = lp;
        split2(of[ni][2] * il1, of[ni][3] * il1, hp, lp);
        *reinterpret_cast<uint32_t*>(&atth[(size_t)(rg + 8) * OW + col]) = hp;
        *reinterpret_cast<uint32_t*>(&attl[(size_t)(rg + 8) * OW + col]) = lp;
    }
}

// ---------------- launch ----------------
extern "C" void kernel_launch(void* const* d_in, const int* in_sizes, int n_in,
                              void* d_out, int out_size)
{
    (void)in_sizes; (void)n_in; (void)out_size;
    const float* hidden = (const float*)d_in[0];
    const float* w_qa   = (const float*)d_in[1];
    const float* g_qa   = (const float*)d_in[2];
    const float* w_qb   = (const float*)d_in[3];
    const float* w_kva  = (const float*)d_in[4];
    const float* g_kva  = (const float*)d_in[5];
    const float* w_kvb  = (const float*)d_in[6];
    const float* w_o    = (const float*)d_in[7];
    float* out = (float*)d_out;

    float *qa, *q, *ckv;
    cudaGetSymbolAddress((void**)&qa,   d_qa);
    cudaGetSymbolAddress((void**)&q,    d_q);
    cudaGetSymbolAddress((void**)&ckv,  d_ckv);

    __nv_bfloat16 *hidh,*hidl,*wqah,*wqal,*wkvah,*wkval,*wqbh,*wqbl,*wkvbh,*wkvbl,*woh,*wol;
    __nv_bfloat16 *qanh,*qanl,*ckvnh,*ckvnl,*kvh,*kvl,*kpeh,*kpel,*atth,*attl;
    cudaGetSymbolAddress((void**)&hidh, d_hidh);   cudaGetSymbolAddress((void**)&hidl, d_hidl);
    cudaGetSymbolAddress((void**)&wqah, d_wqah);   cudaGetSymbolAddress((void**)&wqal, d_wqal);
    cudaGetSymbolAddress((void**)&wkvah, d_wkvah); cudaGetSymbolAddress((void**)&wkval, d_wkval);
    cudaGetSymbolAddress((void**)&wqbh, d_wqbh);   cudaGetSymbolAddress((void**)&wqbl, d_wqbl);
    cudaGetSymbolAddress((void**)&wkvbh, d_wkvbh); cudaGetSymbolAddress((void**)&wkvbl, d_wkvbl);
    cudaGetSymbolAddress((void**)&woh, d_woh);     cudaGetSymbolAddress((void**)&wol, d_wol);
    cudaGetSymbolAddress((void**)&qanh, d_qanh);   cudaGetSymbolAddress((void**)&qanl, d_qanl);
    cudaGetSymbolAddress((void**)&ckvnh, d_ckvnh); cudaGetSymbolAddress((void**)&ckvnl, d_ckvnl);
    cudaGetSymbolAddress((void**)&kvh, d_kvh);     cudaGetSymbolAddress((void**)&kvl, d_kvl);
    cudaGetSymbolAddress((void**)&kpeh, d_kpeh);   cudaGetSymbolAddress((void**)&kpel, d_kpel);
    cudaGetSymbolAddress((void**)&atth, d_atth);   cudaGetSymbolAddress((void**)&attl, d_attl);

    cudaFuncSetAttribute(gemm_bf, cudaFuncAttributeMaxDynamicSharedMemorySize, GEMM_SMEM);
    cudaFuncSetAttribute(gemm_dual, cudaFuncAttributeMaxDynamicSharedMemorySize, GEMM_SMEM);
    cudaFuncSetAttribute(gemm_dual2, cudaFuncAttributeMaxDynamicSharedMemorySize, GEMM_SMEM);
    cudaFuncSetAttribute(flash_tc, cudaFuncAttributeMaxDynamicSharedMemorySize, FLASH_SMEM);

    const dim3 blk(256);

    // 1: all input splits
    splitAll_kernel<<<SPLITALL_ROWS, 256>>>(
        hidden, hidh, hidl, w_qa, wqah, wqal, w_kva, wkvah, wkval,
        w_qb, wqbh, wqbl, w_kvb, wkvbh, wkvbl, w_o, woh, wol);
    // 2: merged qa + ckv GEMM
    gemm_dual<<<dim3(QLORA/128 + (CKVW+127)/128, MTOT/128), blk, GEMM_SMEM>>>(
        hidh, hidl,
        wqah, wqal, qa, QLORA, QLORA/128,
        wkvah, wkval, ckv, CKVW, HDIM);
    // 3: both rmsnorm+split
    rmsnorm2_kernel<<<2 * MTOT, 256>>>(qa, g_qa, qanh, qanl, ckv, g_kva, ckvnh, ckvnl);
    // 4: merged q + kv GEMM (q fp32 out, kv bf16 hi/lo out)
    gemm_dual2<<<dim3(QW/128 + KVW/128, MTOT/128), blk, GEMM_SMEM>>>(
        qanh, qanl, wqbh, wqbl, q, QW, QLORA, QW/128,
        ckvnh, ckvnl, wkvbh, wkvbl, kvh, kvl, KVW, KVLORA);
    // 5: merged rope (q + k)
    rope2_kernel<<<MTOT * NH + MTOT, 32>>>(q, ckv, kpeh, kpel);
    // 6: flash attention (R12 structure)
    flash_tc<<<dim3(SS/128, NH, BB), 256, FLASH_SMEM>>>(q, kvh, kvl, kpeh, kpel, atth, attl);
    // 7: out = attn @ w_o^T
    gemm_bf<<<dim3(HDIM/128, MTOT/128), blk, GEMM_SMEM>>>(atth, attl, woh, wol, out, nullptr, nullptr, HDIM, OW);
}

// round 16
// speedup vs baseline: 1.5661x; 1.0056x over previous
#include <cuda_runtime.h>
#include <cuda_bf16.h>
#include <math.h>
#include <stdint.h>

// ---------------- problem constants ----------------
#define HDIM   2048
#define NH     16
#define QLORA  1536
#define KVLORA 512
#define DN     128
#define DR     64
#define DV     128
#define QD     192
#define BB     2
#define SS     2048
#define MTOT   (BB*SS)      // 4096
#define CKVW   (KVLORA+DR)  // 576
#define KVW    (NH*(DN+DV)) // 4096
#define QW     (NH*QD)      // 3072
#define OW     (NH*DV)      // 2048

// ---------------- fp32 scratch ----------------
__device__ float d_qa  [(size_t)MTOT*QLORA];
__device__ float d_q   [(size_t)MTOT*QW];
__device__ float d_ckv [(size_t)MTOT*CKVW];

// ---------------- bf16 hi/lo scratch ----------------
__device__ __nv_bfloat16 d_hidh [(size_t)MTOT*HDIM],   d_hidl [(size_t)MTOT*HDIM];
__device__ __nv_bfloat16 d_wqah [(size_t)QLORA*HDIM],  d_wqal [(size_t)QLORA*HDIM];
__device__ __nv_bfloat16 d_wkvah[(size_t)CKVW*HDIM],   d_wkval[(size_t)CKVW*HDIM];
__device__ __nv_bfloat16 d_wqbh [(size_t)QW*QLORA],    d_wqbl [(size_t)QW*QLORA];
__device__ __nv_bfloat16 d_wkvbh[(size_t)KVW*KVLORA],  d_wkvbl[(size_t)KVW*KVLORA];
__device__ __nv_bfloat16 d_woh  [(size_t)HDIM*OW],     d_wol  [(size_t)HDIM*OW];
__device__ __nv_bfloat16 d_qanh [(size_t)MTOT*QLORA],  d_qanl [(size_t)MTOT*QLORA];
__device__ __nv_bfloat16 d_ckvnh[(size_t)MTOT*KVLORA], d_ckvnl[(size_t)MTOT*KVLORA];
__device__ __nv_bfloat16 d_kvh  [(size_t)MTOT*KVW],    d_kvl  [(size_t)MTOT*KVW];
__device__ __nv_bfloat16 d_kpeh [(size_t)MTOT*DR],     d_kpel [(size_t)MTOT*DR];
__device__ __nv_bfloat16 d_atth [(size_t)MTOT*OW],     d_attl [(size_t)MTOT*OW];

// ---------------- helpers ----------------
__device__ __forceinline__ uint32_t smem_u32(const void* p) {
    uint32_t a;
    asm("{ .reg .u64 t; cvta.to.shared.u64 t, %1; cvt.u32.u64 %0, t; }" : "=r"(a) : "l"(p));
    return a;
}

__device__ __forceinline__ void ldsm4(uint32_t r[4], uint32_t addr) {
    asm volatile("ldmatrix.sync.aligned.m8n8.x4.shared.b16 {%0,%1,%2,%3}, [%4];"
                 : "=r"(r[0]), "=r"(r[1]), "=r"(r[2]), "=r"(r[3]) : "r"(addr));
}

__device__ __forceinline__ void ldsm4t(uint32_t r[4], uint32_t addr) {
    asm volatile("ldmatrix.sync.aligned.m8n8.x4.trans.shared.b16 {%0,%1,%2,%3}, [%4];"
                 : "=r"(r[0]), "=r"(r[1]), "=r"(r[2]), "=r"(r[3]) : "r"(addr));
}

__device__ __forceinline__ void mma_bf16(float c[4], const uint32_t a[4],
                                         uint32_t b0, uint32_t b1) {
    asm volatile(
        "mma.sync.aligned.m16n8k16.row.col.f32.bf16.bf16.f32 "
        "{%0,%1,%2,%3}, {%4,%5,%6,%7}, {%8,%9}, {%0,%1,%2,%3};"
        : "+f"(c[0]), "+f"(c[1]), "+f"(c[2]), "+f"(c[3])
        : "r"(a[0]), "r"(a[1]), "r"(a[2]), "r"(a[3]), "r"(b0), "r"(b1));
}

__device__ __forceinline__ void split2(float x, float y, uint32_t& hp, uint32_t& lp) {
    __nv_bfloat16 hx = __float2bfloat16(x), hy = __float2bfloat16(y);
    __nv_bfloat16 lx = __float2bfloat16(x - __bfloat162float(hx));
    __nv_bfloat16 ly = __float2bfloat16(y - __bfloat162float(hy));
    hp = ((uint32_t)__bfloat16_as_ushort(hy) << 16) | __bfloat16_as_ushort(hx);
    lp = ((uint32_t)__bfloat16_as_ushort(ly) << 16) | __bfloat16_as_ushort(lx);
}

__device__ __forceinline__ uint32_t sw64(uint32_t o)   { return o ^ ((o >> 3) & 0x30); }
__device__ __forceinline__ uint32_t swz256(uint32_t o) { return o ^ (((o >> 8) & 7) << 4); }

__device__ __forceinline__ void cpa16(uint32_t dst, const void* src) {
    asm volatile("cp.async.cg.shared.global [%0], [%1], 16;" :: "r"(dst), "l"(src));
}
__device__ __forceinline__ void cpa16p(uint32_t dst, const void* src, bool valid) {
    int sz = valid ? 16 : 0;
    asm volatile("cp.async.cg.shared.global [%0], [%1], 16, %2;" :: "r"(dst), "l"(src), "r"(sz));
}
#define CPA_COMMIT() asm volatile("cp.async.commit_group;" ::: "memory")
#define CPA_WAIT1()  asm volatile("cp.async.wait_group 1;" ::: "memory")
#define CPA_WAIT0()  asm volatile("cp.async.wait_group 0;" ::: "memory")

// ---------------- merged fp32 -> bf16 hi/lo split (all 6 tensors) ----------------
__device__ __forceinline__ void split_row(const float* __restrict__ p, int cols,
                                          __nv_bfloat16* __restrict__ h,
                                          __nv_bfloat16* __restrict__ l)
{
    uint32_t* hp = reinterpret_cast<uint32_t*>(h);
    uint32_t* lp = reinterpret_cast<uint32_t*>(l);
    for (int i = threadIdx.x * 4; i < cols; i += blockDim.x * 4) {
        float4 v = *reinterpret_cast<const float4*>(p + i);
        uint32_t h0, l0, h1, l1;
        split2(v.x, v.y, h0, l0);
        split2(v.z, v.w, h1, l1);
        hp[i/2] = h0; hp[i/2+1] = h1;
        lp[i/2] = l0; lp[i/2+1] = l1;
    }
}

__global__ void splitAll_kernel(
    const float* __restrict__ hid, __nv_bfloat16* __restrict__ hidh, __nv_bfloat16* __restrict__ hidl,
    const float* __restrict__ wqa, __nv_bfloat16* __restrict__ wqah, __nv_bfloat16* __restrict__ wqal,
    const float* __restrict__ wkva, __nv_bfloat16* __restrict__ wkvah, __nv_bfloat16* __restrict__ wkval,
    const float* __restrict__ wqb, __nv_bfloat16* __restrict__ wqbh, __nv_bfloat16* __restrict__ wqbl,
    const float* __restrict__ wkvb, __nv_bfloat16* __restrict__ wkvbh, __nv_bfloat16* __restrict__ wkvbl,
    const float* __restrict__ wo, __nv_bfloat16* __restrict__ woh, __nv_bfloat16* __restrict__ wol)
{
    int r = blockIdx.x;
    if (r < MTOT) {
        split_row(hid + (size_t)r * HDIM, HDIM, hidh + (size_t)r * HDIM, hidl + (size_t)r * HDIM);
        return;
    }
    r -= MTOT;
    if (r < QLORA) {
        split_row(wqa + (size_t)r * HDIM, HDIM, wqah + (size_t)r * HDIM, wqal + (size_t)r * HDIM);
        return;
    }
    r -= QLORA;
    if (r < CKVW) {
        split_row(wkva + (size_t)r * HDIM, HDIM, wkvah + (size_t)r * HDIM, wkval + (size_t)r * HDIM);
        return;
    }
    r -= CKVW;
    if (r < QW) {
        split_row(wqb + (size_t)r * QLORA, QLORA, wqbh + (size_t)r * QLORA, wqbl + (size_t)r * QLORA);
        return;
    }
    r -= QW;
    if (r < KVW) {
        split_row(wkvb + (size_t)r * KVLORA, KVLORA, wkvbh + (size_t)r * KVLORA, wkvbl + (size_t)r * KVLORA);
        return;
    }
    r -= KVW;
    split_row(wo + (size_t)r * OW, OW, woh + (size_t)r * OW, wol + (size_t)r * OW);
}
#define SPLITALL_ROWS (MTOT + QLORA + CKVW + QW + KVW + HDIM)

// ---------------- fused RMSNorm + split (both norms, segmented) ----------------
__device__ __forceinline__ void rms_row(const float* __restrict__ p, const float* __restrict__ g,
                                        int D, __nv_bfloat16* __restrict__ h,
                                        __nv_bfloat16* __restrict__ l, float* sred)
{
    float ss = 0.f;
    for (int i = threadIdx.x; i < D; i += blockDim.x) { float v = p[i]; ss += v * v; }
    #pragma unroll
    for (int o = 16; o > 0; o >>= 1) ss += __shfl_xor_sync(0xffffffffu, ss, o);
    if ((threadIdx.x & 31) == 0) sred[threadIdx.x >> 5] = ss;
    __syncthreads();
    if (threadIdx.x < 8) {
        float v = sred[threadIdx.x];
        #pragma unroll
        for (int o = 4; o > 0; o >>= 1) v += __shfl_xor_sync(0xffu, v, o);
        if (threadIdx.x == 0) sred[0] = v;
    }
    __syncthreads();
    const float inv = rsqrtf(sred[0] / (float)D + 1e-6f);
    uint32_t* hp = reinterpret_cast<uint32_t*>(h);
    uint32_t* lp = reinterpret_cast<uint32_t*>(l);
    for (int i = threadIdx.x * 4; i < D; i += blockDim.x * 4) {
        float4 v = *reinterpret_cast<const float4*>(p + i);
        v.x *= inv * g[i]; v.y *= inv * g[i+1]; v.z *= inv * g[i+2]; v.w *= inv * g[i+3];
        uint32_t h0, l0, h1, l1;
        split2(v.x, v.y, h0, l0);
        split2(v.z, v.w, h1, l1);
        hp[i/2] = h0; hp[i/2+1] = h1;
        lp[i/2] = l0; lp[i/2+1] = l1;
    }
}

__global__ void rmsnorm2_kernel(
    const float* __restrict__ qa, const float* __restrict__ gqa,
    __nv_bfloat16* __restrict__ qanh, __nv_bfloat16* __restrict__ qanl,
    const float* __restrict__ ckv, const float* __restrict__ gkva,
    __nv_bfloat16* __restrict__ ckvnh, __nv_bfloat16* __restrict__ ckvnl)
{
    __shared__ float sred[8];
    int r = blockIdx.x;
    if (r < MTOT) {
        rms_row(qa + (size_t)r * QLORA, gqa, QLORA,
                qanh + (size_t)r * QLORA, qanl + (size_t)r * QLORA, sred);
    } else {
        r -= MTOT;
        rms_row(ckv + (size_t)r * CKVW, gkva, KVLORA,
                ckvnh + (size_t)r * KVLORA, ckvnl + (size_t)r * KVLORA, sred);
    }
}

// ---------------- bf16x3 GEMM core, 3-stage cp.async pipeline ----------------
// R16: single __syncthreads per chunk (3-stage ring makes the 2nd redundant).
#define GS_AH 0
#define GS_AL 8192
#define GS_BH 16384
#define GS_BL 24576
#define GS_STAGE 32768
#define GEMM_SMEM (3*GS_STAGE)

__device__ __forceinline__ void gemm_core(
    const __nv_bfloat16* __restrict__ Ah, const __nv_bfloat16* __restrict__ Al,
    const __nv_bfloat16* __restrict__ Bh, const __nv_bfloat16* __restrict__ Bl,
    float* __restrict__ C, __nv_bfloat16* __restrict__ Ch, __nv_bfloat16* __restrict__ Cl,
    int N, int K, int bm, int bn, char* sm)
{
    const uint32_t sb = smem_u32(sm);
    const int tid = threadIdx.x;
    const int NC = K >> 5;

    const int w = tid >> 5, lane = tid & 31;
    const int wm = (w & 1) * 64;
    const int wn = (w >> 1) * 32;
    const int mi  = lane >> 3;
    const int aro = (lane & 7) + (mi & 1) * 8;
    const int aks = (mi >> 1) * 8;
    const int bro = (lane & 7) + ((mi >> 1) & 1) * 8;
    const int bks = (mi & 1) * 8;

    float acc[4][4][4] = {};

    const int lr0 = tid >> 2;
    const int lc0 = tid & 3;
    const int lr1 = (256 + tid) >> 2;
    const int lc1 = (256 + tid) & 3;
    const uint32_t do0 = sw64((uint32_t)(lr0 * 64 + lc0 * 16));
    const uint32_t do1 = sw64((uint32_t)(lr1 * 64 + lc1 * 16));
    const bool bok0 = (bn + lr0) < N;
    const bool bok1 = (bn + lr1) < N;

    auto issue = [&](int c) {
        const int k0 = c << 5;
        const uint32_t st = sb + (uint32_t)(c % 3) * GS_STAGE;
        {
            const size_t go = (size_t)(bm + lr0) * K + k0 + lc0 * 8;
            cpa16(st + GS_AH + do0, Ah + go);
            cpa16(st + GS_AL + do0, Al + go);
            const size_t gb = (size_t)(bn + lr0) * K + k0 + lc0 * 8;
            cpa16p(st + GS_BH + do0, Bh + gb, bok0);
            cpa16p(st + GS_BL + do0, Bl + gb, bok0);
        }
        {
            const size_t go = (size_t)(bm + lr1) * K + k0 + lc1 * 8;
            cpa16(st + GS_AH + do1, Ah + go);
            cpa16(st + GS_AL + do1, Al + go);
            const size_t gb = (size_t)(bn + lr1) * K + k0 + lc1 * 8;
            cpa16p(st + GS_BH + do1, Bh + gb, bok1);
            cpa16p(st + GS_BL + do1, Bl + gb, bok1);
        }
        CPA_COMMIT();
    };

    auto compute = [&](int c) {
        const uint32_t st = sb + (uint32_t)(c % 3) * GS_STAGE;
        #pragma unroll
        for (int k16 = 0; k16 < 32; k16 += 16) {
            uint32_t A_h[4][4], B_h[2][4];
            #pragma unroll
            for (int f = 0; f < 4; f++) {
                const uint32_t x = (uint32_t)((wm + f * 16 + aro) * 64 + (k16 + aks) * 2);
                ldsm4(A_h[f], st + GS_AH + sw64(x));
            }
            #pragma unroll
            for (int g2 = 0; g2 < 2; g2++) {
                const uint32_t x = (uint32_t)((wn + g2 * 16 + bro) * 64 + (k16 + bks) * 2);
                ldsm4(B_h[g2], st + GS_BH + sw64(x));
            }
            #pragma unroll
            for (int f = 0; f < 4; f++)
                #pragma unroll
                for (int ni = 0; ni < 4; ni++)
                    mma_bf16(acc[f][ni], A_h[f], B_h[ni >> 1][(ni & 1) * 2],
                             B_h[ni >> 1][(ni & 1) * 2 + 1]);
            {
                uint32_t B_l[2][4];
                #pragma unroll
                for (int g2 = 0; g2 < 2; g2++) {
                    const uint32_t x = (uint32_t)((wn + g2 * 16 + bro) * 64 + (k16 + bks) * 2);
                    ldsm4(B_l[g2], st + GS_BL + sw64(x));
                }
                #pragma unroll
                for (int f = 0; f < 4; f++)
                    #pragma unroll
                    for (int ni = 0; ni < 4; ni++)
                        mma_bf16(acc[f][ni], A_h[f], B_l[ni >> 1][(ni & 1) * 2],
                                 B_l[ni >> 1][(ni & 1) * 2 + 1]);
            }
            {
                uint32_t A_l[4][4];
                #pragma unroll
                for (int f = 0; f < 4; f++) {
                    const uint32_t x = (uint32_t)((wm + f * 16 + aro) * 64 + (k16 + aks) * 2);
                    ldsm4(A_l[f], st + GS_AL + sw64(x));
                }
                #pragma unroll
                for (int f = 0; f < 4; f++)
                    #pragma unroll
                    for (int ni = 0; ni < 4; ni++)
                        mma_bf16(acc[f][ni], A_l[f], B_h[ni >> 1][(ni & 1) * 2],
                                 B_h[ni >> 1][(ni & 1) * 2 + 1]);
            }
        }
    };

    // single barrier per chunk: the sync after CPA_WAIT guarantees every warp
    // finished compute(c-1) before anyone overwrites stage (c+2)%3 == (c-1)%3.
    issue(0);
    issue(1);
    for (int c = 0; c < NC; c++) {
        if (c + 1 < NC) CPA_WAIT1(); else CPA_WAIT0();
        __syncthreads();
        if (c + 2 < NC) issue(c + 2);
        compute(c);
    }

    const int gq = lane >> 2, t4 = lane & 3;
    if (C) {
        #pragma unroll
        for (int f = 0; f < 4; f++)
            #pragma unroll
            for (int ni = 0; ni < 4; ni++) {
                const int col = bn + wn + ni * 8 + t4 * 2;
                if (col < N) {
                    const int r = bm + wm + f * 16 + gq;
                    *reinterpret_cast<float2*>(&C[(size_t)r * N + col]) =
                        make_float2(acc[f][ni][0], acc[f][ni][1]);
                    *reinterpret_cast<float2*>(&C[(size_t)(r + 8) * N + col]) =
                        make_float2(acc[f][ni][2], acc[f][ni][3]);
                }
            }
    } else {
        #pragma unroll
        for (int f = 0; f < 4; f++)
            #pragma unroll
            for (int ni = 0; ni < 4; ni++) {
                const int col = bn + wn + ni * 8 + t4 * 2;
                if (col < N) {
                    const int r = bm + wm + f * 16 + gq;
                    uint32_t hp, lp;
                    split2(acc[f][ni][0], acc[f][ni][1], hp, lp);
                    *reinterpret_cast<uint32_t*>(&Ch[(size_t)r * N + col]) = hp;
                    *reinterpret_cast<uint32_t*>(&Cl[(size_t)r * N + col]) = lp;
                    split2(acc[f][ni][2], acc[f][ni][3], hp, lp);
                    *reinterpret_cast<uint32_t*>(&Ch[(size_t)(r + 8) * N + col]) = hp;
                    *reinterpret_cast<uint32_t*>(&Cl[(size_t)(r + 8) * N + col]) = lp;
                }
            }
    }
}

__global__ __launch_bounds__(256, 2) void gemm_bf(
    const __nv_bfloat16* __restrict__ Ah, const __nv_bfloat16* __restrict__ Al,
    const __nv_bfloat16* __restrict__ Bh, const __nv_bfloat16* __restrict__ Bl,
    float* __restrict__ C, __nv_bfloat16* __restrict__ Ch, __nv_bfloat16* __restrict__ Cl,
    int N, int K)
{
    extern __shared__ char sm[];
    gemm_core(Ah, Al, Bh, Bl, C, Ch, Cl, N, K, blockIdx.y * 128, blockIdx.x * 128, sm);
}

__global__ __launch_bounds__(256, 2) void gemm_dual(
    const __nv_bfloat16* __restrict__ Ah, const __nv_bfloat16* __restrict__ Al,
    const __nv_bfloat16* __restrict__ B1h, const __nv_bfloat16* __restrict__ B1l,
    float* __restrict__ C1, int N1, int split,
    const __nv_bfloat16* __restrict__ B2h, const __nv_bfloat16* __restrict__ B2l,
    float* __restrict__ C2, int N2, int K)
{
    extern __shared__ char sm[];
    const int bx = blockIdx.x;
    if (bx < split)
        gemm_core(Ah, Al, B1h, B1l, C1, nullptr, nullptr, N1, K,
                  blockIdx.y * 128, bx * 128, sm);
    else
        gemm_core(Ah, Al, B2h, B2l, C2, nullptr, nullptr, N2, K,
                  blockIdx.y * 128, (bx - split) * 128, sm);
}

__global__ __launch_bounds__(256, 2) void gemm_dual2(
    const __nv_bfloat16* __restrict__ A1h, const __nv_bfloat16* __restrict__ A1l,
    const __nv_bfloat16* __restrict__ B1h, const __nv_bfloat16* __restrict__ B1l,
    float* __restrict__ C1, int N1, int K1, int split,
    const __nv_bfloat16* __restrict__ A2h, const __nv_bfloat16* __restrict__ A2l,
    const __nv_bfloat16* __restrict__ B2h, const __nv_bfloat16* __restrict__ B2l,
    __nv_bfloat16* __restrict__ C2h, __nv_bfloat16* __restrict__ C2l, int N2, int K2)
{
    extern __shared__ char sm[];
    const int bx = blockIdx.x;
    if (bx < split)
        gemm_core(A1h, A1l, B1h, B1l, C1, nullptr, nullptr, N1, K1,
                  blockIdx.y * 128, bx * 128, sm);
    else
        gemm_core(A2h, A2l, B2h, B2l, nullptr, C2h, C2l, N2, K2,
                  blockIdx.y * 128, (bx - split) * 128, sm);
}

// ---------------- merged RoPE (q segment + k segment) ----------------
__global__ void rope2_kernel(float* __restrict__ q, const float* __restrict__ ckv,
                             __nv_bfloat16* __restrict__ kpeh, __nv_bfloat16* __restrict__ kpel)
{
    const int j = threadIdx.x;
    const double inv = exp(-log(10000.0) * (2.0 * j) / (double)DR);
    if (blockIdx.x < MTOT * NH) {
        const int idx = blockIdx.x;
        const int row = idx / NH, h = idx % NH;
        const int t = row % SS;
        const double ang = (double)t * inv;
        const float c = (float)cos(ang), s = (float)sin(ang);
        float* p = q + (size_t)row * QW + h * QD + DN;
        const float x0 = p[j], x1 = p[j + 32];
        p[j]      = x0 * c - x1 * s;
        p[j + 32] = x1 * c + x0 * s;
    } else {
        const int row = blockIdx.x - MTOT * NH;
        const int t = row % SS;
        const double ang = (double)t * inv;
        const float c = (float)cos(ang), s = (float)sin(ang);
        const float* p = ckv + (size_t)row * CKVW + KVLORA;
        const float x0 = p[j], x1 = p[j + 32];
        const float y0 = x0 * c - x1 * s;
        const float y1 = x1 * c + x0 * s;
        __nv_bfloat16 h0 = __float2bfloat16(y0);
        __nv_bfloat16 h1 = __float2bfloat16(y1);
        kpeh[(size_t)row * DR + j]      = h0;
        kpeh[(size_t)row * DR + j + 32] = h1;
        kpel[(size_t)row * DR + j]      = __float2bfloat16(y0 - __bfloat162float(h0));
        kpel[(size_t)row * DR + j + 32] = __float2bfloat16(y1 - __bfloat162float(h1));
    }
}

// ---------------- tensor-core causal flash attention (R12) ----------------
#define FQH 0                 // 6*8192 = 49152
#define FQL 49152
#define FKB 98304             // stage s at FKB + s*49152; KH +0, KL +24576
#define FVB 196608            // VH +0, VL +16384
#define FLASH_SMEM 229376

__global__ __launch_bounds__(256) void flash_tc(
    const float* __restrict__ q,
    const __nv_bfloat16* __restrict__ kvh, const __nv_bfloat16* __restrict__ kvl,
    const __nv_bfloat16* __restrict__ kpeh, const __nv_bfloat16* __restrict__ kpel,
    __nv_bfloat16* __restrict__ atth, __nv_bfloat16* __restrict__ attl)
{
    extern __shared__ char sm[];
    const uint32_t sb = smem_u32(sm);

    const int qb = (int)gridDim.x - 1 - (int)blockIdx.x;   // longest-first
    const int h = blockIdx.y, b = blockIdx.z;
    const int tid = threadIdx.x;
    const int w = tid >> 5, lane = tid & 31;
    const int g = lane >> 2, t4 = lane & 3;
    const int mi  = lane >> 3;
    const int aro = (lane & 7) + (mi & 1) * 8;
    const int aks = (mi >> 1) * 8;
    const int bro = (lane & 7) + ((mi >> 1) & 1) * 8;
    const int bks = (mi & 1) * 8;
    const int hoff = h * (DN + DV);

    const int q0 = qb * 128;
    const int row0 = b * SS + q0;
    const int brow = b * SS;
    const float scale = rsqrtf((float)QD);
    const int n_tiles = 2 * qb + 2;

    auto issueK = [&](int kt) {
        const uint32_t base = sb + FKB + (kt & 1) * 49152;
        const int krow = brow + kt * 64;
        #pragma unroll
        for (int t = 0; t < 12; t++) {
            const int idx = t * 256 + tid;
            const int half = idx >= 1536;
            const int cidx = half ? idx - 1536 : idx;
            const int key = cidx / 24;
            const int c = cidx % 24;
            const int d = (c < 16) ? c * 8 : 128 + (c - 16) * 8;
            const uint32_t dst = base + (half ? 24576u : 0u) + (uint32_t)(d >> 5) * 4096
                               + sw64((uint32_t)(key * 64 + (d & 31) * 2));
            const __nv_bfloat16* src;
            if (c < 16) src = (half ? kvl : kvh) + (size_t)(krow + key) * KVW + hoff + d;
            else        src = (half ? kpel : kpeh) + (size_t)(krow + key) * DR + (d - 128);
            cpa16(dst, src);
        }
    };
    auto issueV = [&](int kt) {
        const int krow = brow + kt * 64;
        #pragma unroll
        for (int t = 0; t < 8; t++) {
            const int idx = t * 256 + tid;
            const int half = idx >= 1024;
            const int cidx = idx & 1023;
            const int key = cidx >> 4;
            const int d = (cidx & 15) * 8;
            const uint32_t dst = sb + FVB + (half ? 16384u : 0u)
                               + swz256((uint32_t)(key * 256 + d * 2));
            const __nv_bfloat16* src = (half ? kvl : kvh) + (size_t)(krow + key) * KVW + hoff + DN + d;
            cpa16(dst, src);
        }
    };

    #pragma unroll
    for (int t = 0; t < 24; t++) {
        const int idx = t * 256 + tid;
        const int r = idx / 48;
        const int c4 = (idx % 48) * 4;
        float4 v = *reinterpret_cast<const float4*>(&q[(size_t)(row0 + r) * QW + h * QD + c4]);
        v.x *= scale; v.y *= scale; v.z *= scale; v.w *= scale;
        const uint32_t off = (uint32_t)(c4 >> 5) * 8192 + sw64((uint32_t)(r * 64 + (c4 & 31) * 2));
        uint32_t h0, l0, h1, l1;
        split2(v.x, v.y, h0, l0);
        split2(v.z, v.w, h1, l1);
        *reinterpret_cast<uint2*>(sm + FQH + off) = make_uint2(h0, h1);
        *reinterpret_cast<uint2*>(sm + FQL + off) = make_uint2(l0, l1);
    }

    issueK(0);
    issueV(0);
    CPA_COMMIT();

    float of[16][4] = {};
    float m0 = -INFINITY, m1 = -INFINITY, l0 = 0.f, l1 = 0.f;

    for (int kt = 0; kt < n_tiles; kt++) {
        if (kt + 1 < n_tiles) { issueK(kt + 1); CPA_COMMIT(); CPA_WAIT1(); }
        else                  { CPA_WAIT0(); }
        __syncthreads();

        const int k0 = kt * 64;
        const uint32_t kbase = sb + FKB + (kt & 1) * 49152;

        float sf[8][4] = {};
        const uint32_t qax = (uint32_t)((w * 16 + aro) * 64 + aks * 2);
        #pragma unroll
        for (int s = 0; s < 12; s++) {
            uint32_t ah[4], al[4];
            const uint32_t qoff = (uint32_t)(s >> 1) * 8192 + sw64(qax + (s & 1) * 32);
            ldsm4(ah, sb + FQH + qoff);
            ldsm4(al, sb + FQL + qoff);
            uint32_t bh[4][4], bl[4][4];
            #pragma unroll
            for (int g2 = 0; g2 < 4; g2++) {
                const uint32_t kx = (uint32_t)((g2 * 16 + bro) * 64 + bks * 2);
                const uint32_t koff = (uint32_t)(s >> 1) * 4096 + sw64(kx + (s & 1) * 32);
                ldsm4(bh[g2], kbase + koff);
                ldsm4(bl[g2], kbase + 24576 + koff);
            }
            #pragma unroll
            for (int g2 = 0; g2 < 4; g2++)
                #pragma unroll
                for (int sub = 0; sub < 2; sub++)
                    mma_bf16(sf[g2 * 2 + sub], ah, bh[g2][sub * 2], bh[g2][sub * 2 + 1]);
            #pragma unroll
            for (int g2 = 0; g2 < 4; g2++)
                #pragma unroll
                for (int sub = 0; sub < 2; sub++)
                    mma_bf16(sf[g2 * 2 + sub], ah, bl[g2][sub * 2], bl[g2][sub * 2 + 1]);
            #pragma unroll
            for (int g2 = 0; g2 < 4; g2++)
                #pragma unroll
                for (int sub = 0; sub < 2; sub++)
                    mma_bf16(sf[g2 * 2 + sub], al, bh[g2][sub * 2], bh[g2][sub * 2 + 1]);
        }

        if (kt >= 2 * qb) {
            const int qr0 = q0 + w * 16 + g;
            const int qr8 = qr0 + 8;
            #pragma unroll
            for (int ni = 0; ni < 8; ni++) {
                const int kp0 = k0 + ni * 8 + 2 * t4;
                const int kp1 = kp0 + 1;
                if (kp0 > qr0) sf[ni][0] = -1e30f;
                if (kp1 > qr0) sf[ni][1] = -1e30f;
                if (kp0 > qr8) sf[ni][2] = -1e30f;
                if (kp1 > qr8) sf[ni][3] = -1e30f;
            }
        }

        float tm0 = -INFINITY, tm1 = -INFINITY;
        #pragma unroll
        for (int ni = 0; ni < 8; ni++) {
            tm0 = fmaxf(tm0, fmaxf(sf[ni][0], sf[ni][1]));
            tm1 = fmaxf(tm1, fmaxf(sf[ni][2], sf[ni][3]));
        }
        #pragma unroll
        for (int o = 1; o < 4; o <<= 1) {
            tm0 = fmaxf(tm0, __shfl_xor_sync(0xffffffffu, tm0, o));
            tm1 = fmaxf(tm1, __shfl_xor_sync(0xffffffffu, tm1, o));
        }
        const float mn0 = fmaxf(m0, tm0), mn1 = fmaxf(m1, tm1);
        const float a0 = __expf(m0 - mn0), a1 = __expf(m1 - mn1);
        float ls0 = 0.f, ls1 = 0.f;
        #pragma unroll
        for (int ni = 0; ni < 8; ni++) {
            sf[ni][0] = __expf(sf[ni][0] - mn0); ls0 += sf[ni][0];
            sf[ni][1] = __expf(sf[ni][1] - mn0); ls0 += sf[ni][1];
            sf[ni][2] = __expf(sf[ni][2] - mn1); ls1 += sf[ni][2];
            sf[ni][3] = __expf(sf[ni][3] - mn1); ls1 += sf[ni][3];
        }
        #pragma unroll
        for (int o = 1; o < 4; o <<= 1) {
            ls0 += __shfl_xor_sync(0xffffffffu, ls0, o);
            ls1 += __shfl_xor_sync(0xffffffffu, ls1, o);
        }
        l0 = l0 * a0 + ls0; l1 = l1 * a1 + ls1;
        m0 = mn0; m1 = mn1;
        #pragma unroll
        for (int ni = 0; ni < 16; ni++) {
            of[ni][0] *= a0; of[ni][1] *= a0;
            of[ni][2] *= a1; of[ni][3] *= a1;
        }

        #pragma unroll
        for (int ks = 0; ks < 4; ks++) {
            uint32_t ph[4], pl[4];
            split2(sf[2*ks][0],   sf[2*ks][1],   ph[0], pl[0]);
            split2(sf[2*ks][2],   sf[2*ks][3],   ph[1], pl[1]);
            split2(sf[2*ks+1][0], sf[2*ks+1][1], ph[2], pl[2]);
            split2(sf[2*ks+1][2], sf[2*ks+1][3], ph[3], pl[3]);
            const int vkey = ks * 16 + (mi & 1) * 8 + (lane & 7);
            const int vdvo = (mi >> 1) * 8;
            #pragma unroll
            for (int gp = 0; gp < 4; gp++) {
                uint32_t vh[2][4], vl[2][4];
                #pragma unroll
                for (int j = 0; j < 2; j++) {
                    const int g2 = gp * 2 + j;
                    const uint32_t vo = swz256((uint32_t)(vkey * 256 + (g2 * 16 + vdvo) * 2));
                    ldsm4t(vh[j], sb + FVB + vo);
                    ldsm4t(vl[j], sb + FVB + 16384 + vo);
                }
                #pragma unroll
                for (int j = 0; j < 2; j++)
                    #pragma unroll
                    for (int sub = 0; sub < 2; sub++)
                        mma_bf16(of[(gp * 2 + j) * 2 + sub], ph, vh[j][sub * 2], vh[j][sub * 2 + 1]);
                #pragma unroll
                for (int j = 0; j < 2; j++)
                    #pragma unroll
                    for (int sub = 0; sub < 2; sub++)
                        mma_bf16(of[(gp * 2 + j) * 2 + sub], ph, vl[j][sub * 2], vl[j][sub * 2 + 1]);
                #pragma unroll
                for (int j = 0; j < 2; j++)
                    #pragma unroll
                    for (int sub = 0; sub < 2; sub++)
                        mma_bf16(of[(gp * 2 + j) * 2 + sub], pl, vh[j][sub * 2], vh[j][sub * 2 + 1]);
            }
        }
        __syncthreads();
        if (kt + 1 < n_tiles) { issueV(kt + 1); CPA_COMMIT(); }
    }

    const float il0 = 1.f / l0, il1 = 1.f / l1;
    const int rg = row0 + w * 16 + g;
    #pragma unroll
    for (int ni = 0; ni < 16; ni++) {
        const int col = h * DV + ni * 8 + t4 * 2;
        uint32_t hp, lp;
        split2(of[ni][0] * il0, of[ni][1] * il0, hp, lp);
        *reinterpret_cast<uint32_t*>(&atth[(size_t)rg * OW + col]) = hp;
        *reinterpret_cast<uint32_t*>(&attl[(size_t)rg * OW + col]) = lp;
        split2(of[ni][2] * il1, of[ni][3] * il1, hp, lp);
        *reinterpret_cast<uint32_t*>(&atth[(size_t)(rg + 8) * OW + col]) = hp;
        *reinterpret_cast<uint32_t*>(&attl[(size_t)(rg + 8) * OW + col]) = lp;
    }
}

// ---------------- launch ----------------
extern "C" void kernel_launch(void* const* d_in, const int* in_sizes, int n_in,
                              void* d_out, int out_size)
{
    (void)in_sizes; (void)n_in; (void)out_size;
    const float* hidden = (const float*)d_in[0];
    const float* w_qa   = (const float*)d_in[1];
    const float* g_qa   = (const float*)d_in[2];
    const float* w_qb   = (const float*)d_in[3];
    const float* w_kva  = (const float*)d_in[4];
    const float* g_kva  = (const float*)d_in[5];
    const float* w_kvb  = (const float*)d_in[6];
    const float* w_o    = (const float*)d_in[7];
    float* out = (float*)d_out;

    float *qa, *q, *ckv;
    cudaGetSymbolAddress((void**)&qa,   d_qa);
    cudaGetSymbolAddress((void**)&q,    d_q);
    cudaGetSymbolAddress((void**)&ckv,  d_ckv);

    __nv_bfloat16 *hidh,*hidl,*wqah,*wqal,*wkvah,*wkval,*wqbh,*wqbl,*wkvbh,*wkvbl,*woh,*wol;
    __nv_bfloat16 *qanh,*qanl,*ckvnh,*ckvnl,*kvh,*kvl,*kpeh,*kpel,*atth,*attl;
    cudaGetSymbolAddress((void**)&hidh, d_hidh);   cudaGetSymbolAddress((void**)&hidl, d_hidl);
    cudaGetSymbolAddress((void**)&wqah, d_wqah);   cudaGetSymbolAddress((void**)&wqal, d_wqal);
    cudaGetSymbolAddress((void**)&wkvah, d_wkvah); cudaGetSymbolAddress((void**)&wkval, d_wkval);
    cudaGetSymbolAddress((void**)&wqbh, d_wqbh);   cudaGetSymbolAddress((void**)&wqbl, d_wqbl);
    cudaGetSymbolAddress((void**)&wkvbh, d_wkvbh); cudaGetSymbolAddress((void**)&wkvbl, d_wkvbl);
    cudaGetSymbolAddress((void**)&woh, d_woh);     cudaGetSymbolAddress((void**)&wol, d_wol);
    cudaGetSymbolAddress((void**)&qanh, d_qanh);   cudaGetSymbolAddress((void**)&qanl, d_qanl);
    cudaGetSymbolAddress((void**)&ckvnh, d_ckvnh); cudaGetSymbolAddress((void**)&ckvnl, d_ckvnl);
    cudaGetSymbolAddress((void**)&kvh, d_kvh);     cudaGetSymbolAddress((void**)&kvl, d_kvl);
    cudaGetSymbolAddress((void**)&kpeh, d_kpeh);   cudaGetSymbolAddress((void**)&kpel, d_kpel);
    cudaGetSymbolAddress((void**)&atth, d_atth);   cudaGetSymbolAddress((void**)&attl, d_attl);

    cudaFuncSetAttribute(gemm_bf, cudaFuncAttributeMaxDynamicSharedMemorySize, GEMM_SMEM);
    cudaFuncSetAttribute(gemm_dual, cudaFuncAttributeMaxDynamicSharedMemorySize, GEMM_SMEM);
    cudaFuncSetAttribute(gemm_dual2, cudaFuncAttributeMaxDynamicSharedMemorySize, GEMM_SMEM);
    cudaFuncSetAttribute(flash_tc, cudaFuncAttributeMaxDynamicSharedMemorySize, FLASH_SMEM);

    const dim3 blk(256);

    // 1: all input splits
    splitAll_kernel<<<SPLITALL_ROWS, 256>>>(
        hidden, hidh, hidl, w_qa, wqah, wqal, w_kva, wkvah, wkval,
        w_qb, wqbh, wqbl, w_kvb, wkvbh, wkvbl, w_o, woh, wol);
    // 2: merged qa + ckv GEMM
    gemm_dual<<<dim3(QLORA/128 + (CKVW+127)/128, MTOT/128), blk, GEMM_SMEM>>>(
        hidh, hidl,
        wqah, wqal, qa, QLORA, QLORA/128,
        wkvah, wkval, ckv, CKVW, HDIM);
    // 3: both rmsnorm+split
    rmsnorm2_kernel<<<2 * MTOT, 256>>>(qa, g_qa, qanh, qanl, ckv, g_kva, ckvnh, ckvnl);
    // 4: merged q + kv GEMM (q fp32 out, kv bf16 hi/lo out)
    gemm_dual2<<<dim3(QW/128 + KVW/128, MTOT/128), blk, GEMM_SMEM>>>(
        qanh, qanl, wqbh, wqbl, q, QW, QLORA, QW/128,
        ckvnh, ckvnl, wkvbh, wkvbl, kvh, kvl, KVW, KVLORA);
    // 5: merged rope (q + k)
    rope2_kernel<<<MTOT * NH + MTOT, 32>>>(q, ckv, kpeh, kpel);
    // 6: flash attention (R12 structure)
    flash_tc<<<dim3(SS/128, NH, BB), 256, FLASH_SMEM>>>(q, kvh, kvl, kpeh, kpel, atth, attl);
    // 7: out = attn @ w_o^T
    gemm_bf<<<dim3(HDIM/128, MTOT/128), blk, GEMM_SMEM>>>(atth, attl, woh, wol, out, nullptr, nullptr, HDIM, OW);
}